// round 12
// baseline (speedup 1.0000x reference)
#include <cuda_runtime.h>
#include <cuda_fp16.h>
#include <cstdint>

#define SLOPE 0.01f
#define Dn 17
#define Hn 256
#define En 64
#define NCB 136
#define Bn 16384

// smem byte offsets (main kernel)
#define SM_X     0        // 128 floats
#define SM_W1    512      // 256 floats
#define SM_B1    1536     // 256 floats
#define SM_BM0   2560     // 256 floats
#define SM_BM1   3584     // 256 floats
#define SM_BC    4608     // 136 floats
#define SM_BBUF  5248     // 2 x 17408 B pair double-buffer (chunk slots at +0 / +8704)
#define SM_ANX   40064    // 8 warps x 16 slots x 32 lanes x 16B = 64KB (A-frag spill)
#define SM_TOTAL (40064 + 65536)

// ---- static device scratch (no allocation) ----
__device__ float g_q [(size_t)Bn * Dn * En];
__device__ float g_k [(size_t)Bn * Dn * En];
__device__ float g_vs[(size_t)Bn * Dn * 4];
__device__ float g_Wcomb[Dn * Hn * NCB];
__device__ float g_bcomb[Dn * NCB];
__device__ float g_cv[4 * En];
__device__ float g_dv[4];
__device__ float g_const;
// fragment-ordered fp16 weight blobs; each uint4 = {hi.b0, hi.b1, lo.b0, lo.b1}
// mid: per mat (l*17+i): [h*16+kt][ntl][lane] -> 16384 uint4
__device__ uint4 g_Bmid[(size_t)2 * Dn * 16384];
// fin: per i: [kt][nt][lane] -> 8704 uint4
__device__ uint4 g_Bfin[(size_t)Dn * 8704];

__device__ __forceinline__ float lrelu(float v) { return v >= 0.f ? v : SLOPE * v; }

// pack two f32 -> f16x2 (first arg -> bits[15:0], second -> bits[31:16])
__device__ __forceinline__ uint32_t pkh(float lo, float hi) {
    uint32_t r;
    asm("cvt.rn.f16x2.f32 %0, %1, %2;" : "=r"(r) : "f"(hi), "f"(lo));
    return r;
}
__device__ __forceinline__ float f16res(float v) {
    return v - __half2float(__float2half_rn(v));
}

// fp32-accumulator MMA (hi pass)
__device__ __forceinline__ void mma16816(float* d, const uint32_t* a, uint32_t b0, uint32_t b1) {
    asm volatile(
        "mma.sync.aligned.m16n8k16.row.col.f32.f16.f16.f32 "
        "{%0,%1,%2,%3}, {%4,%5,%6,%7}, {%8,%9}, {%0,%1,%2,%3};"
        : "+f"(d[0]), "+f"(d[1]), "+f"(d[2]), "+f"(d[3])
        : "r"(a[0]), "r"(a[1]), "r"(a[2]), "r"(a[3]), "r"(b0), "r"(b1));
}
// fp16-accumulator MMA (lo pass; result is a tiny correction term)
__device__ __forceinline__ void mma16816h(uint32_t* d, const uint32_t* a, uint32_t b0, uint32_t b1) {
    asm volatile(
        "mma.sync.aligned.m16n8k16.row.col.f16.f16.f16.f16 "
        "{%0,%1}, {%2,%3,%4,%5}, {%6,%7}, {%0,%1};"
        : "+r"(d[0]), "+r"(d[1])
        : "r"(a[0]), "r"(a[1]), "r"(a[2]), "r"(a[3]), "r"(b0), "r"(b1));
}

__device__ __forceinline__ void cpa16(void* sdst, const void* gsrc) {
    uint32_t s = (uint32_t)__cvta_generic_to_shared(sdst);
    asm volatile("cp.async.cg.shared.global [%0], [%1], 16;" :: "r"(s), "l"(gsrc));
}
#define CPCOMMIT() asm volatile("cp.async.commit_group;")
#define CPWAIT(n)  asm volatile("cp.async.wait_group %0;" :: "n"(n))

// ============================ setup kernels ============================
__global__ void setup1_kernel(const float* __restrict__ Wv, const float* __restrict__ bv,
                              const float* __restrict__ Wo, const float* __restrict__ bo,
                              const float* __restrict__ Wfc, const float* __restrict__ bfc)
{
    __shared__ float us[64];
    int t = threadIdx.x;
    float s = 0.f;
    for (int e = 0; e < 64; e++) s += Wo[e * 64 + t] * Wfc[e];
    us[t] = s;
    __syncthreads();
    for (int h = 0; h < 4; h++) {
        float c = 0.f;
        for (int j = 0; j < 16; j++) c += Wv[(h * 16 + j) * 64 + t] * us[h * 16 + j];
        g_cv[h * 64 + t] = c;
    }
    if (t < 4) {
        float dsum = 0.f;
        for (int j = 0; j < 16; j++) dsum += bv[t * 16 + j] * us[t * 16 + j];
        g_dv[t] = dsum;
    }
    if (t == 0) {
        float c = bfc[0];
        for (int e = 0; e < 64; e++) c += bo[e] * Wfc[e];
        g_const = c;
    }
}

__global__ void setup2_kernel(const float* __restrict__ Wf, const float* __restrict__ bf,
                              const float* __restrict__ Wq, const float* __restrict__ bq,
                              const float* __restrict__ Wk, const float* __restrict__ bk)
{
    __shared__ float Wqs[4096], Wks[4096], cvs[256];
    int t = threadIdx.x, i = blockIdx.x;
    #pragma unroll
    for (int u = 0; u < 16; u++) {
        int idx = t + 256 * u;
        Wqs[idx] = Wq[idx];
        Wks[idx] = Wk[idx];
    }
    cvs[t] = g_cv[t];
    __syncthreads();

    int k = t;
    float wf[64];
    #pragma unroll
    for (int tt = 0; tt < 64; tt++) wf[tt] = Wf[((size_t)i * 256 + k) * 64 + tt];
    float* dst = g_Wcomb + ((size_t)i * 256 + k) * NCB;
    for (int e = 0; e < 64; e++) {
        float sq = 0.f, sk = 0.f;
        #pragma unroll
        for (int tt = 0; tt < 64; tt++) { sq += wf[tt] * Wqs[e * 64 + tt]; sk += wf[tt] * Wks[e * 64 + tt]; }
        dst[e] = sq; dst[64 + e] = sk;
    }
    #pragma unroll
    for (int h = 0; h < 4; h++) {
        float sv = 0.f;
        #pragma unroll
        for (int tt = 0; tt < 64; tt++) sv += wf[tt] * cvs[h * 64 + tt];
        dst[128 + h] = sv;
    }
    dst[132] = dst[133] = dst[134] = dst[135] = 0.f;

    if (t < NCB) {
        float v;
        if (t < 64) {
            v = bq[t];
            for (int tt = 0; tt < 64; tt++) v += bf[i * 64 + tt] * Wqs[t * 64 + tt];
        } else if (t < 128) {
            int e = t - 64; v = bk[e];
            for (int tt = 0; tt < 64; tt++) v += bf[i * 64 + tt] * Wks[e * 64 + tt];
        } else if (t < 132) {
            int h = t - 128; v = g_dv[h];
            for (int tt = 0; tt < 64; tt++) v += bf[i * 64 + tt] * cvs[h * 64 + tt];
        } else v = 0.f;
        g_bcomb[i * NCB + t] = v;
    }
}

// middle-layer weights -> fp16 hi/lo fragment blobs. grid 34*8 blocks.
__global__ void setup_midblob_kernel(const float* __restrict__ Wm)
{
    int mat = blockIdx.x >> 3, part = blockIdx.x & 7;
    const float* W = Wm + (size_t)mat * 65536;
    uint4* dst = g_Bmid + (size_t)mat * 16384;
    for (int idx = part * 2048 + threadIdx.x; idx < (part + 1) * 2048; idx += 256) {
        int lane = idx & 31;
        int ntl  = (idx >> 5) & 15;
        int kt   = (idx >> 9) & 15;
        int h    = (idx >> 13) & 1;
        int n  = (h * 16 + ntl) * 8 + (lane >> 2);
        int k0 = kt * 16 + (lane & 3) * 2;
        float w0 = W[(k0 + 0) * 256 + n], w1 = W[(k0 + 1) * 256 + n];
        float w8 = W[(k0 + 8) * 256 + n], w9 = W[(k0 + 9) * 256 + n];
        uint4 v;
        v.x = pkh(w0, w1);
        v.y = pkh(w8, w9);
        v.z = pkh(f16res(w0), f16res(w1));
        v.w = pkh(f16res(w8), f16res(w9));
        dst[idx] = v;
    }
}

// final combined weights -> fp16 hi/lo fragment blobs. grid 17*2 blocks.
__global__ void setup_finblob_kernel()
{
    int i = blockIdx.x >> 1, part = blockIdx.x & 1;
    uint4* dst = g_Bfin + (size_t)i * 8704;
    int lo_i = part * 4352, hi_i = lo_i + 4352;
    const float* W = g_Wcomb + (size_t)i * 256 * NCB;
    for (int idx = lo_i + threadIdx.x; idx < hi_i; idx += 256) {
        int lane = idx & 31;
        int q  = idx >> 5;
        int nt = q % 17;
        int kt = q / 17;
        int n  = nt * 8 + (lane >> 2);
        int k0 = kt * 16 + (lane & 3) * 2;
        float w0 = W[(k0 + 0) * NCB + n], w1 = W[(k0 + 1) * NCB + n];
        float w8 = W[(k0 + 8) * NCB + n], w9 = W[(k0 + 9) * NCB + n];
        uint4 v;
        v.x = pkh(w0, w1);
        v.y = pkh(w8, w9);
        v.z = pkh(f16res(w0), f16res(w1));
        v.w = pkh(f16res(w8), f16res(w9));
        dst[idx] = v;
    }
}

// ============================ main kernel ============================
// pair p = two chunks staged into the two 8704B slots of buffer (p&1).
// mid chunks are 8192B (512 uint4); fin chunks are 8704B (544 uint4).
// Consumer always reads chunk `half` at byte offset half*8704.
__device__ __forceinline__ void stage_pair(char* smem, int p, int i, int t)
{
    char* dst = smem + SM_BBUF + (p & 1) * 17408;
    if (p < 32) {
        int layer = p >> 4, rem2 = p & 15;
        const char* src = (const char*)(g_Bmid + (size_t)(layer * Dn + i) * 16384 + (size_t)rem2 * 1024);
        // chunk 0: 8192B at slot +0 ; chunk 1: 8192B at slot +8704
        #pragma unroll
        for (int u = 0; u < 2; u++) {
            int o = (t + u * 256) * 16;
            cpa16(dst + o,        src + o);
            cpa16(dst + 8704 + o, src + 8192 + o);
        }
    } else {
        const char* src = (const char*)(g_Bfin + (size_t)i * 8704 + (size_t)(p - 32) * 1088);
        #pragma unroll
        for (int u = 0; u < 5; u++) {
            int o = t + u * 256;
            if (o < 1088) cpa16(dst + o * 16, src + o * 16);
        }
    }
}

__global__ void __launch_bounds__(256, 1) subnet_mma_kernel(
    const float* __restrict__ x, const float* __restrict__ W1,
    const float* __restrict__ b1, const float* __restrict__ bm)
{
    extern __shared__ char smem[];
    float* xs   = (float*)(smem + SM_X);
    float* w1s  = (float*)(smem + SM_W1);
    float* b1s  = (float*)(smem + SM_B1);
    float* bm0s = (float*)(smem + SM_BM0);
    float* bm1s = (float*)(smem + SM_BM1);
    float* bcs  = (float*)(smem + SM_BC);

    const int t = threadIdx.x, w = t >> 5, lane = t & 31;
    const int gr = lane >> 2, c = lane & 3;
    const int i  = blockIdx.y, r0 = blockIdx.x * 128;

    // stage pair 0 ASAP
    stage_pair(smem, 0, i, t);
    CPCOMMIT();

    // stage constants
    if (t < 128) xs[t] = x[(size_t)(r0 + t) * Dn + i];
    w1s[t]  = W1[i * 256 + t];
    b1s[t]  = b1[i * 256 + t];
    bm0s[t] = bm[(0 * Dn + i) * 256 + t];
    bm1s[t] = bm[(1 * Dn + i) * 256 + t];
    if (t < NCB) bcs[t] = g_bcomb[i * NCB + t];
    __syncthreads();

    // ---- first layer: outer product -> A fragments (fp16, regs only) ----
    uint32_t Ahi[16][4];
    {
        float xa = xs[w * 16 + gr];
        float xb = xs[w * 16 + gr + 8];
        #pragma unroll
        for (int kt = 0; kt < 16; kt++) {
            int c0 = kt * 16 + 2 * c;
            float W0 = w1s[c0], W1v = w1s[c0 + 1], W8 = w1s[c0 + 8], W9 = w1s[c0 + 9];
            float B0 = b1s[c0], B1v = b1s[c0 + 1], B8 = b1s[c0 + 8], B9 = b1s[c0 + 9];
            Ahi[kt][0] = pkh(lrelu(fmaf(xa, W0, B0)), lrelu(fmaf(xa, W1v, B1v)));
            Ahi[kt][1] = pkh(lrelu(fmaf(xb, W0, B0)), lrelu(fmaf(xb, W1v, B1v)));
            Ahi[kt][2] = pkh(lrelu(fmaf(xa, W8, B8)), lrelu(fmaf(xa, W9, B9)));
            Ahi[kt][3] = pkh(lrelu(fmaf(xb, W8, B8)), lrelu(fmaf(xb, W9, B9)));
        }
    }

    // warp-staggered start offsets (break cross-warp phase alignment)
    const int roff16 = (2 * w) & 15;        // mid layers
    const int roff17 = (2 * w) % 17;        // final layer

    // ---- two middle 256x256 layers ----
    #pragma unroll 1
    for (int layer = 0; layer < 2; layer++) {
        const float* bmls = (layer == 0) ? bm0s : bm1s;

        #pragma unroll
        for (int h = 0; h < 2; h++) {
            float acc[16][4];
            uint32_t accL[16][2];
            #pragma unroll
            for (int n_ = 0; n_ < 16; n_++) {
                #pragma unroll
                for (int r = 0; r < 4; r++) acc[n_][r] = 0.f;
                accL[n_][0] = 0u; accL[n_][1] = 0u;
            }

            #pragma unroll
            for (int ktp = 0; ktp < 8; ktp++) {
                const int p = layer * 16 + h * 8 + ktp;
                __syncthreads();   // consumers of pair p-1 done -> buffer (p+1)&1 free
                if (p < 39) { stage_pair(smem, p + 1, i, t); CPCOMMIT(); CPWAIT(1); }
                else        { CPWAIT(0); }
                __syncthreads();   // pair p fully staged for all threads

                const char* bb = smem + SM_BBUF + (p & 1) * 17408;
                #pragma unroll
                for (int half = 0; half < 2; half++) {
                    const char* bc2 = bb + half * 8704;
                    const int kt = 2 * ktp + half;
                    // staggered + software-pipelined inner loop
                    uint4 cur = *(const uint4*)(bc2 + (roff16 * 32 + lane) * 16);
                    int ntl = roff16;
                    #pragma unroll
                    for (int j = 0; j < 16; j++) {
                        int ntn = (ntl + 1) & 15;
                        uint4 nxt = (j < 15) ? *(const uint4*)(bc2 + (ntn * 32 + lane) * 16) : cur;
                        mma16816 (acc [ntl], Ahi[kt], cur.x, cur.y);   // A * W_hi (f32 acc)
                        mma16816h(accL[ntl], Ahi[kt], cur.z, cur.w);   // A * W_lo (f16 acc)
                        cur = nxt;
                        ntl = ntn;
                    }
                }
            }

            // epilogue: merge lo, bias + lrelu, pack -> smem A-frag slots (thread-private)
            #pragma unroll
            for (int j = 0; j < 8; j++) {
                int nt0 = 2 * j, nt1 = 2 * j + 1;
                int cb = 128 * h + 16 * j + 2 * c;
                float2 l00 = __half22float2(*(__half2*)&accL[nt0][0]);
                float2 l01 = __half22float2(*(__half2*)&accL[nt0][1]);
                float2 l10 = __half22float2(*(__half2*)&accL[nt1][0]);
                float2 l11 = __half22float2(*(__half2*)&accL[nt1][1]);
                float2 bb0 = *(const float2*)(bmls + cb);
                float2 bb1 = *(const float2*)(bmls + cb + 8);
                uint4 frag;
                frag.x = pkh(lrelu(acc[nt0][0] + l00.x + bb0.x), lrelu(acc[nt0][1] + l00.y + bb0.y));
                frag.y = pkh(lrelu(acc[nt0][2] + l01.x + bb0.x), lrelu(acc[nt0][3] + l01.y + bb0.y));
                frag.z = pkh(lrelu(acc[nt1][0] + l10.x + bb1.x), lrelu(acc[nt1][1] + l10.y + bb1.y));
                frag.w = pkh(lrelu(acc[nt1][2] + l11.x + bb1.x), lrelu(acc[nt1][3] + l11.y + bb1.y));
                *(uint4*)(smem + SM_ANX + (((w * 16) + 8 * h + j) * 32 + lane) * 16) = frag;
            }
        }

        // reload next-layer A-frags from thread-private smem slots (no sync needed)
        #pragma unroll
        for (int q = 0; q < 16; q++) {
            uint4 v = *(const uint4*)(smem + SM_ANX + ((w * 16 + q) * 32 + lane) * 16);
            Ahi[q][0] = v.x; Ahi[q][1] = v.y; Ahi[q][2] = v.z; Ahi[q][3] = v.w;
        }
    }

    // ---- final layer: 256 -> 136 (q | k | vs) ----
    {
        float fac[17][4];
        uint32_t facL[17][2];
        #pragma unroll
        for (int n_ = 0; n_ < 17; n_++) {
            #pragma unroll
            for (int r = 0; r < 4; r++) fac[n_][r] = 0.f;
            facL[n_][0] = 0u; facL[n_][1] = 0u;
        }

        #pragma unroll
        for (int ktp2 = 0; ktp2 < 8; ktp2++) {
            const int p = 32 + ktp2;
            __syncthreads();
            if (p < 39) { stage_pair(smem, p + 1, i, t); CPCOMMIT(); CPWAIT(1); }
            else        { CPWAIT(0); }
            __syncthreads();

            const char* bb = smem + SM_BBUF + (p & 1) * 17408;
            #pragma unroll
            for (int half = 0; half < 2; half++) {
                const char* bc2 = bb + half * 8704;
                const int kt = 2 * ktp2 + half;
                uint4 cur = *(const uint4*)(bc2 + (roff17 * 32 + lane) * 16);
                int nt = roff17;
                #pragma unroll
                for (int j = 0; j < 17; j++) {
                    int ntn = (nt + 1 == 17) ? 0 : nt + 1;
                    uint4 nxt = (j < 16) ? *(const uint4*)(bc2 + (ntn * 32 + lane) * 16) : cur;
                    mma16816 (fac [nt], Ahi[kt], cur.x, cur.y);
                    mma16816h(facL[nt], Ahi[kt], cur.z, cur.w);
                    cur = nxt;
                    nt = ntn;
                }
            }
        }

        // epilogue: merge lo, bias + scatter to g_q / g_k / g_vs
        const int row0 = r0 + w * 16 + gr, row1 = row0 + 8;
        #pragma unroll
        for (int nt = 0; nt < 17; nt++) {
            int col = nt * 8 + 2 * c;
            float2 l0 = __half22float2(*(__half2*)&facL[nt][0]);
            float2 l1 = __half22float2(*(__half2*)&facL[nt][1]);
            float2 bb = *(const float2*)(bcs + col);
            float2 o0 = make_float2(fac[nt][0] + l0.x + bb.x, fac[nt][1] + l0.y + bb.y);
            float2 o1 = make_float2(fac[nt][2] + l1.x + bb.x, fac[nt][3] + l1.y + bb.y);
            if (nt < 8) {
                *(float2*)&g_q[((size_t)row0 * Dn + i) * En + col] = o0;
                *(float2*)&g_q[((size_t)row1 * Dn + i) * En + col] = o1;
            } else if (nt < 16) {
                *(float2*)&g_k[((size_t)row0 * Dn + i) * En + (col - 64)] = o0;
                *(float2*)&g_k[((size_t)row1 * Dn + i) * En + (col - 64)] = o1;
            } else if (c < 2) {
                *(float2*)&g_vs[((size_t)row0 * Dn + i) * 4 + (col - 128)] = o0;
                *(float2*)&g_vs[((size_t)row1 * Dn + i) * 4 + (col - 128)] = o1;
            }
        }
    }
}

// ============================ attention-lite kernel ============================
#define QS2 68
__global__ void __launch_bounds__(256, 2) attn_kernel(float* __restrict__ out)
{
    extern __shared__ float smemf[];
    const int t = threadIdx.x, wid = t >> 5, lane = t & 31;
    float* qs  = smemf + wid * (2 * Dn * QS2 + 68);
    float* ks  = qs + Dn * QS2;
    float* vss = ks + Dn * QS2;

    const int row = blockIdx.x * 8 + wid;
    const float* qr = g_q + (size_t)row * (Dn * En);
    const float* kr = g_k + (size_t)row * (Dn * En);

    #pragma unroll
    for (int u = 0; u < 34; u++) {
        int o = u * 32 + lane;
        int ii = o >> 6, e = o & 63;
        qs[ii * QS2 + e] = qr[o];
        ks[ii * QS2 + e] = kr[o];
    }
    #pragma unroll
    for (int u = 0; u < 3; u++) {
        int p = u * 32 + lane;
        if (p < 68) vss[p] = g_vs[(size_t)row * 68 + p];
    }
    __syncwarp();

    float partial = 0.f;
    #pragma unroll
    for (int u = 0; u < 3; u++) {
        int p = u * 32 + lane;
        if (p < 68) {
            int h = p / 17, i1 = p - h * 17;
            const float* qv = qs + i1 * QS2 + h * 16;
            float s[17], smax = -1e30f;
            #pragma unroll
            for (int i2 = 0; i2 < 17; i2++) {
                const float* kv = ks + i2 * QS2 + h * 16;
                float d = 0.f;
                #pragma unroll
                for (int j = 0; j < 16; j++) d += qv[j] * kv[j];
                d *= 0.25f;
                s[i2] = d;
                smax = fmaxf(smax, d);
            }
            float den = 0.f, num = 0.f;
            #pragma unroll
            for (int i2 = 0; i2 < 17; i2++) {
                float e = __expf(s[i2] - smax);
                den += e;
                num += e * vss[i2 * 4 + h];
            }
            partial += num / den;
        }
    }
    #pragma unroll
    for (int off = 16; off; off >>= 1)
        partial += __shfl_down_sync(0xffffffffu, partial, off);
    if (lane == 0) out[row] = lrelu(partial * (1.f / 17.f) + g_const);
}

// ---------------------------------------------------------------------------
extern "C" void kernel_launch(void* const* d_in, const int* in_sizes, int n_in,
                              void* d_out, int out_size)
{
    const float* x   = (const float*)d_in[0];
    const float* W1  = (const float*)d_in[1];
    const float* b1  = (const float*)d_in[2];
    const float* Wm  = (const float*)d_in[3];
    const float* bm  = (const float*)d_in[4];
    const float* Wf  = (const float*)d_in[5];
    const float* bf  = (const float*)d_in[6];
    const float* Wq  = (const float*)d_in[7];
    const float* bq  = (const float*)d_in[8];
    const float* Wk  = (const float*)d_in[9];
    const float* bk  = (const float*)d_in[10];
    const float* Wv  = (const float*)d_in[11];
    const float* bv  = (const float*)d_in[12];
    const float* Wo  = (const float*)d_in[13];
    const float* bo  = (const float*)d_in[14];
    const float* Wfc = (const float*)d_in[15];
    const float* bfc = (const float*)d_in[16];
    float* out = (float*)d_out;

    const int k2_smem = 8 * (2 * Dn * QS2 + 68) * (int)sizeof(float);

    cudaFuncSetAttribute(subnet_mma_kernel, cudaFuncAttributeMaxDynamicSharedMemorySize, SM_TOTAL);
    cudaFuncSetAttribute(attn_kernel,       cudaFuncAttributeMaxDynamicSharedMemorySize, k2_smem);

    setup1_kernel<<<1, 64>>>(Wv, bv, Wo, bo, Wfc, bfc);
    setup2_kernel<<<Dn, 256>>>(Wf, bf, Wq, bq, Wk, bk);
    setup_midblob_kernel<<<2 * Dn * 8, 256>>>(Wm);
    setup_finblob_kernel<<<Dn * 2, 256>>>();

    dim3 g1(Bn / 128, Dn);
    subnet_mma_kernel<<<g1, 256, SM_TOTAL>>>(x, W1, b1, bm);

    attn_kernel<<<Bn / 8, 256, k2_smem>>>(out);
}

// round 13
// speedup vs baseline: 4.8193x; 4.8193x over previous
#include <cuda_runtime.h>
#include <cuda_fp16.h>
#include <cstdint>

#define SLOPE 0.01f
#define Dn 17
#define Hn 256
#define En 64
#define NCB 136
#define Bn 16384

// smem byte offsets (main kernel)
#define SM_X     0        // 128 floats
#define SM_W1    512      // 256 floats
#define SM_B1    1536     // 256 floats
#define SM_BM0   2560     // 256 floats
#define SM_BM1   3584     // 256 floats
#define SM_BC    4608     // 136 floats
#define SM_BBUF  5248     // 2 x 34816 B quad double-buffer (4 chunk slots of 8704B each)
#define SM_ANX   74880    // 8 warps x 16 slots x 32 lanes x 16B = 64KB (A-frag spill)
#define SM_TOTAL (74880 + 65536)

// ---- static device scratch (no allocation) ----
__device__ float g_q [(size_t)Bn * Dn * En];
__device__ float g_k [(size_t)Bn * Dn * En];
__device__ float g_vs[(size_t)Bn * Dn * 4];
__device__ float g_Wcomb[Dn * Hn * NCB];
__device__ float g_bcomb[Dn * NCB];
__device__ float g_cv[4 * En];
__device__ float g_dv[4];
__device__ float g_const;
// fragment-ordered fp16 weight blobs; each uint4 = {hi.b0, hi.b1, lo.b0, lo.b1}
// mid: per mat (l*17+i): [h*16+kt][ntl][lane] -> 16384 uint4 (32 chunks x 512)
__device__ uint4 g_Bmid[(size_t)2 * Dn * 16384];
// fin: per i: [kt][nt][lane] -> 8704 uint4 (16 chunks x 544)
__device__ uint4 g_Bfin[(size_t)Dn * 8704];

__device__ __forceinline__ float lrelu(float v) { return v >= 0.f ? v : SLOPE * v; }

// pack two f32 -> f16x2 (first arg -> bits[15:0], second -> bits[31:16])
__device__ __forceinline__ uint32_t pkh(float lo, float hi) {
    uint32_t r;
    asm("cvt.rn.f16x2.f32 %0, %1, %2;" : "=r"(r) : "f"(hi), "f"(lo));
    return r;
}
__device__ __forceinline__ float f16res(float v) {
    return v - __half2float(__float2half_rn(v));
}

// fp32-accumulator MMA (hi pass)
__device__ __forceinline__ void mma16816(float* d, const uint32_t* a, uint32_t b0, uint32_t b1) {
    asm volatile(
        "mma.sync.aligned.m16n8k16.row.col.f32.f16.f16.f32 "
        "{%0,%1,%2,%3}, {%4,%5,%6,%7}, {%8,%9}, {%0,%1,%2,%3};"
        : "+f"(d[0]), "+f"(d[1]), "+f"(d[2]), "+f"(d[3])
        : "r"(a[0]), "r"(a[1]), "r"(a[2]), "r"(a[3]), "r"(b0), "r"(b1));
}
// fp16-accumulator MMA (lo pass; result is a tiny correction term)
__device__ __forceinline__ void mma16816h(uint32_t* d, const uint32_t* a, uint32_t b0, uint32_t b1) {
    asm volatile(
        "mma.sync.aligned.m16n8k16.row.col.f16.f16.f16.f16 "
        "{%0,%1}, {%2,%3,%4,%5}, {%6,%7}, {%0,%1};"
        : "+r"(d[0]), "+r"(d[1])
        : "r"(a[0]), "r"(a[1]), "r"(a[2]), "r"(a[3]), "r"(b0), "r"(b1));
}

__device__ __forceinline__ void cpa16(void* sdst, const void* gsrc) {
    uint32_t s = (uint32_t)__cvta_generic_to_shared(sdst);
    asm volatile("cp.async.cg.shared.global [%0], [%1], 16;" :: "r"(s), "l"(gsrc));
}
#define CPCOMMIT() asm volatile("cp.async.commit_group;")
#define CPWAIT(n)  asm volatile("cp.async.wait_group %0;" :: "n"(n))

// ============================ setup kernels ============================
__global__ void setup1_kernel(const float* __restrict__ Wv, const float* __restrict__ bv,
                              const float* __restrict__ Wo, const float* __restrict__ bo,
                              const float* __restrict__ Wfc, const float* __restrict__ bfc)
{
    __shared__ float us[64];
    int t = threadIdx.x;
    float s = 0.f;
    for (int e = 0; e < 64; e++) s += Wo[e * 64 + t] * Wfc[e];
    us[t] = s;
    __syncthreads();
    for (int h = 0; h < 4; h++) {
        float c = 0.f;
        for (int j = 0; j < 16; j++) c += Wv[(h * 16 + j) * 64 + t] * us[h * 16 + j];
        g_cv[h * 64 + t] = c;
    }
    if (t < 4) {
        float dsum = 0.f;
        for (int j = 0; j < 16; j++) dsum += bv[t * 16 + j] * us[t * 16 + j];
        g_dv[t] = dsum;
    }
    if (t == 0) {
        float c = bfc[0];
        for (int e = 0; e < 64; e++) c += bo[e] * Wfc[e];
        g_const = c;
    }
}

__global__ void setup2_kernel(const float* __restrict__ Wf, const float* __restrict__ bf,
                              const float* __restrict__ Wq, const float* __restrict__ bq,
                              const float* __restrict__ Wk, const float* __restrict__ bk)
{
    __shared__ float Wqs[4096], Wks[4096], cvs[256];
    int t = threadIdx.x, i = blockIdx.x;
    #pragma unroll
    for (int u = 0; u < 16; u++) {
        int idx = t + 256 * u;
        Wqs[idx] = Wq[idx];
        Wks[idx] = Wk[idx];
    }
    cvs[t] = g_cv[t];
    __syncthreads();

    int k = t;
    float wf[64];
    #pragma unroll
    for (int tt = 0; tt < 64; tt++) wf[tt] = Wf[((size_t)i * 256 + k) * 64 + tt];
    float* dst = g_Wcomb + ((size_t)i * 256 + k) * NCB;
    for (int e = 0; e < 64; e++) {
        float sq = 0.f, sk = 0.f;
        #pragma unroll
        for (int tt = 0; tt < 64; tt++) { sq += wf[tt] * Wqs[e * 64 + tt]; sk += wf[tt] * Wks[e * 64 + tt]; }
        dst[e] = sq; dst[64 + e] = sk;
    }
    #pragma unroll
    for (int h = 0; h < 4; h++) {
        float sv = 0.f;
        #pragma unroll
        for (int tt = 0; tt < 64; tt++) sv += wf[tt] * cvs[h * 64 + tt];
        dst[128 + h] = sv;
    }
    dst[132] = dst[133] = dst[134] = dst[135] = 0.f;

    if (t < NCB) {
        float v;
        if (t < 64) {
            v = bq[t];
            for (int tt = 0; tt < 64; tt++) v += bf[i * 64 + tt] * Wqs[t * 64 + tt];
        } else if (t < 128) {
            int e = t - 64; v = bk[e];
            for (int tt = 0; tt < 64; tt++) v += bf[i * 64 + tt] * Wks[e * 64 + tt];
        } else if (t < 132) {
            int h = t - 128; v = g_dv[h];
            for (int tt = 0; tt < 64; tt++) v += bf[i * 64 + tt] * cvs[h * 64 + tt];
        } else v = 0.f;
        g_bcomb[i * NCB + t] = v;
    }
}

// middle-layer weights -> fp16 hi/lo fragment blobs. grid 34*8 blocks.
__global__ void setup_midblob_kernel(const float* __restrict__ Wm)
{
    int mat = blockIdx.x >> 3, part = blockIdx.x & 7;
    const float* W = Wm + (size_t)mat * 65536;
    uint4* dst = g_Bmid + (size_t)mat * 16384;
    for (int idx = part * 2048 + threadIdx.x; idx < (part + 1) * 2048; idx += 256) {
        int lane = idx & 31;
        int ntl  = (idx >> 5) & 15;
        int kt   = (idx >> 9) & 15;
        int h    = (idx >> 13) & 1;
        int n  = (h * 16 + ntl) * 8 + (lane >> 2);
        int k0 = kt * 16 + (lane & 3) * 2;
        float w0 = W[(k0 + 0) * 256 + n], w1 = W[(k0 + 1) * 256 + n];
        float w8 = W[(k0 + 8) * 256 + n], w9 = W[(k0 + 9) * 256 + n];
        uint4 v;
        v.x = pkh(w0, w1);
        v.y = pkh(w8, w9);
        v.z = pkh(f16res(w0), f16res(w1));
        v.w = pkh(f16res(w8), f16res(w9));
        dst[idx] = v;
    }
}

// final combined weights -> fp16 hi/lo fragment blobs. grid 17*2 blocks.
__global__ void setup_finblob_kernel()
{
    int i = blockIdx.x >> 1, part = blockIdx.x & 1;
    uint4* dst = g_Bfin + (size_t)i * 8704;
    int lo_i = part * 4352, hi_i = lo_i + 4352;
    const float* W = g_Wcomb + (size_t)i * 256 * NCB;
    for (int idx = lo_i + threadIdx.x; idx < hi_i; idx += 256) {
        int lane = idx & 31;
        int q  = idx >> 5;
        int nt = q % 17;
        int kt = q / 17;
        int n  = nt * 8 + (lane >> 2);
        int k0 = kt * 16 + (lane & 3) * 2;
        float w0 = W[(k0 + 0) * NCB + n], w1 = W[(k0 + 1) * NCB + n];
        float w8 = W[(k0 + 8) * NCB + n], w9 = W[(k0 + 9) * NCB + n];
        uint4 v;
        v.x = pkh(w0, w1);
        v.y = pkh(w8, w9);
        v.z = pkh(f16res(w0), f16res(w1));
        v.w = pkh(f16res(w8), f16res(w9));
        dst[idx] = v;
    }
}

// ============================ main kernel ============================
// quad q = four chunks staged into the four 8704B slots of buffer (q&1).
// mid chunks are 8192B (512 uint4); fin chunks are 8704B (544 uint4).
// Consumer reads chunk cc at byte offset cc*8704.
// mid quads q=0..15: layer=q>>3, within-layer chunks 4*(q&7)..+3 (chunk = h*16+kt)
// fin quads q=16..19: chunks 4*(q-16)..+3 of g_Bfin (contiguous 8704B chunks)
__device__ __forceinline__ void stage_quad(char* smem, int q, int i, int t)
{
    char* dst = smem + SM_BBUF + (q & 1) * 34816;
    if (q < 16) {
        int layer = q >> 3, rem4 = q & 7;
        const char* src = (const char*)(g_Bmid + (size_t)(layer * Dn + i) * 16384 + (size_t)rem4 * 2048);
        #pragma unroll
        for (int cc = 0; cc < 4; cc++) {
            #pragma unroll
            for (int u = 0; u < 2; u++) {
                int o = (t + u * 256) * 16;
                cpa16(dst + cc * 8704 + o, src + cc * 8192 + o);
            }
        }
    } else {
        const char* src = (const char*)(g_Bfin + (size_t)i * 8704 + (size_t)(q - 16) * 2176);
        #pragma unroll
        for (int u = 0; u < 9; u++) {
            int o = t + u * 256;
            if (o < 2176) cpa16(dst + o * 16, src + o * 16);
        }
    }
}

__global__ void __launch_bounds__(256, 1) subnet_mma_kernel(
    const float* __restrict__ x, const float* __restrict__ W1,
    const float* __restrict__ b1, const float* __restrict__ bm)
{
    extern __shared__ char smem[];
    float* xs   = (float*)(smem + SM_X);
    float* w1s  = (float*)(smem + SM_W1);
    float* b1s  = (float*)(smem + SM_B1);
    float* bm0s = (float*)(smem + SM_BM0);
    float* bm1s = (float*)(smem + SM_BM1);
    float* bcs  = (float*)(smem + SM_BC);

    const int t = threadIdx.x, w = t >> 5, lane = t & 31;
    const int gr = lane >> 2, c = lane & 3;
    const int i  = blockIdx.y, r0 = blockIdx.x * 128;

    // stage quad 0 ASAP
    stage_quad(smem, 0, i, t);
    CPCOMMIT();

    // stage constants
    if (t < 128) xs[t] = x[(size_t)(r0 + t) * Dn + i];
    w1s[t]  = W1[i * 256 + t];
    b1s[t]  = b1[i * 256 + t];
    bm0s[t] = bm[(0 * Dn + i) * 256 + t];
    bm1s[t] = bm[(1 * Dn + i) * 256 + t];
    if (t < NCB) bcs[t] = g_bcomb[i * NCB + t];
    __syncthreads();

    // ---- first layer: outer product -> A fragments (fp16, regs only) ----
    uint32_t Ahi[16][4];
    {
        float xa = xs[w * 16 + gr];
        float xb = xs[w * 16 + gr + 8];
        #pragma unroll
        for (int kt = 0; kt < 16; kt++) {
            int c0 = kt * 16 + 2 * c;
            float W0 = w1s[c0], W1v = w1s[c0 + 1], W8 = w1s[c0 + 8], W9 = w1s[c0 + 9];
            float B0 = b1s[c0], B1v = b1s[c0 + 1], B8 = b1s[c0 + 8], B9 = b1s[c0 + 9];
            Ahi[kt][0] = pkh(lrelu(fmaf(xa, W0, B0)), lrelu(fmaf(xa, W1v, B1v)));
            Ahi[kt][1] = pkh(lrelu(fmaf(xb, W0, B0)), lrelu(fmaf(xb, W1v, B1v)));
            Ahi[kt][2] = pkh(lrelu(fmaf(xa, W8, B8)), lrelu(fmaf(xa, W9, B9)));
            Ahi[kt][3] = pkh(lrelu(fmaf(xb, W8, B8)), lrelu(fmaf(xb, W9, B9)));
        }
    }

    // ---- two middle 256x256 layers ----
    #pragma unroll 1
    for (int layer = 0; layer < 2; layer++) {
        const float* bmls = (layer == 0) ? bm0s : bm1s;

        #pragma unroll
        for (int h = 0; h < 2; h++) {
            float acc[16][4];
            uint32_t accL[16][2];
            #pragma unroll
            for (int n_ = 0; n_ < 16; n_++) {
                #pragma unroll
                for (int r = 0; r < 4; r++) acc[n_][r] = 0.f;
                accL[n_][0] = 0u; accL[n_][1] = 0u;
            }

            #pragma unroll
            for (int qi = 0; qi < 4; qi++) {
                const int q = layer * 8 + h * 4 + qi;
                __syncthreads();   // consumers of quad q-1 done -> buffer (q+1)&1 free
                if (q < 19) { stage_quad(smem, q + 1, i, t); CPCOMMIT(); CPWAIT(1); }
                else        { CPWAIT(0); }
                __syncthreads();   // quad q fully staged for all threads

                const char* bb = smem + SM_BBUF + (q & 1) * 34816;
                #pragma unroll
                for (int cc = 0; cc < 4; cc++) {
                    const char* bc2 = bb + cc * 8704;
                    const int kt = 4 * qi + cc;
                    #pragma unroll
                    for (int ntl = 0; ntl < 16; ntl++) {
                        uint4 b4 = *(const uint4*)(bc2 + (ntl * 32 + lane) * 16);
                        mma16816 (acc [ntl], Ahi[kt], b4.x, b4.y);   // A * W_hi (f32 acc)
                        mma16816h(accL[ntl], Ahi[kt], b4.z, b4.w);   // A * W_lo (f16 acc)
                    }
                }
            }

            // epilogue: merge lo, bias + lrelu, pack -> smem A-frag slots (thread-private)
            #pragma unroll
            for (int j = 0; j < 8; j++) {
                int nt0 = 2 * j, nt1 = 2 * j + 1;
                int cb = 128 * h + 16 * j + 2 * c;
                float2 l00 = __half22float2(*(__half2*)&accL[nt0][0]);
                float2 l01 = __half22float2(*(__half2*)&accL[nt0][1]);
                float2 l10 = __half22float2(*(__half2*)&accL[nt1][0]);
                float2 l11 = __half22float2(*(__half2*)&accL[nt1][1]);
                float2 bb0 = *(const float2*)(bmls + cb);
                float2 bb1 = *(const float2*)(bmls + cb + 8);
                uint4 frag;
                frag.x = pkh(lrelu(acc[nt0][0] + l00.x + bb0.x), lrelu(acc[nt0][1] + l00.y + bb0.y));
                frag.y = pkh(lrelu(acc[nt0][2] + l01.x + bb0.x), lrelu(acc[nt0][3] + l01.y + bb0.y));
                frag.z = pkh(lrelu(acc[nt1][0] + l10.x + bb1.x), lrelu(acc[nt1][1] + l10.y + bb1.y));
                frag.w = pkh(lrelu(acc[nt1][2] + l11.x + bb1.x), lrelu(acc[nt1][3] + l11.y + bb1.y));
                *(uint4*)(smem + SM_ANX + (((w * 16) + 8 * h + j) * 32 + lane) * 16) = frag;
            }
        }

        // reload next-layer A-frags from thread-private smem slots (no sync needed)
        #pragma unroll
        for (int q2 = 0; q2 < 16; q2++) {
            uint4 v = *(const uint4*)(smem + SM_ANX + ((w * 16 + q2) * 32 + lane) * 16);
            Ahi[q2][0] = v.x; Ahi[q2][1] = v.y; Ahi[q2][2] = v.z; Ahi[q2][3] = v.w;
        }
    }

    // ---- final layer: 256 -> 136 (q | k | vs) ----
    {
        float fac[17][4];
        uint32_t facL[17][2];
        #pragma unroll
        for (int n_ = 0; n_ < 17; n_++) {
            #pragma unroll
            for (int r = 0; r < 4; r++) fac[n_][r] = 0.f;
            facL[n_][0] = 0u; facL[n_][1] = 0u;
        }

        #pragma unroll
        for (int qq = 0; qq < 4; qq++) {
            const int q = 16 + qq;
            __syncthreads();
            if (q < 19) { stage_quad(smem, q + 1, i, t); CPCOMMIT(); CPWAIT(1); }
            else        { CPWAIT(0); }
            __syncthreads();

            const char* bb = smem + SM_BBUF + (q & 1) * 34816;
            #pragma unroll
            for (int cc = 0; cc < 4; cc++) {
                const char* bc2 = bb + cc * 8704;
                const int kt = 4 * qq + cc;
                #pragma unroll
                for (int nt = 0; nt < 17; nt++) {
                    uint4 b4 = *(const uint4*)(bc2 + (nt * 32 + lane) * 16);
                    mma16816 (fac [nt], Ahi[kt], b4.x, b4.y);
                    mma16816h(facL[nt], Ahi[kt], b4.z, b4.w);
                }
            }
        }

        // epilogue: merge lo, bias + scatter to g_q / g_k / g_vs
        const int row0 = r0 + w * 16 + gr, row1 = row0 + 8;
        #pragma unroll
        for (int nt = 0; nt < 17; nt++) {
            int col = nt * 8 + 2 * c;
            float2 l0 = __half22float2(*(__half2*)&facL[nt][0]);
            float2 l1 = __half22float2(*(__half2*)&facL[nt][1]);
            float2 bb = *(const float2*)(bcs + col);
            float2 o0 = make_float2(fac[nt][0] + l0.x + bb.x, fac[nt][1] + l0.y + bb.y);
            float2 o1 = make_float2(fac[nt][2] + l1.x + bb.x, fac[nt][3] + l1.y + bb.y);
            if (nt < 8) {
                *(float2*)&g_q[((size_t)row0 * Dn + i) * En + col] = o0;
                *(float2*)&g_q[((size_t)row1 * Dn + i) * En + col] = o1;
            } else if (nt < 16) {
                *(float2*)&g_k[((size_t)row0 * Dn + i) * En + (col - 64)] = o0;
                *(float2*)&g_k[((size_t)row1 * Dn + i) * En + (col - 64)] = o1;
            } else if (c < 2) {
                *(float2*)&g_vs[((size_t)row0 * Dn + i) * 4 + (col - 128)] = o0;
                *(float2*)&g_vs[((size_t)row1 * Dn + i) * 4 + (col - 128)] = o1;
            }
        }
    }
}

// ============================ attention-lite kernel ============================
#define QS2 68
__global__ void __launch_bounds__(256, 2) attn_kernel(float* __restrict__ out)
{
    extern __shared__ float smemf[];
    const int t = threadIdx.x, wid = t >> 5, lane = t & 31;
    float* qs  = smemf + wid * (2 * Dn * QS2 + 68);
    float* ks  = qs + Dn * QS2;
    float* vss = ks + Dn * QS2;

    const int row = blockIdx.x * 8 + wid;
    const float* qr = g_q + (size_t)row * (Dn * En);
    const float* kr = g_k + (size_t)row * (Dn * En);

    #pragma unroll
    for (int u = 0; u < 34; u++) {
        int o = u * 32 + lane;
        int ii = o >> 6, e = o & 63;
        qs[ii * QS2 + e] = qr[o];
        ks[ii * QS2 + e] = kr[o];
    }
    #pragma unroll
    for (int u = 0; u < 3; u++) {
        int p = u * 32 + lane;
        if (p < 68) vss[p] = g_vs[(size_t)row * 68 + p];
    }
    __syncwarp();

    float partial = 0.f;
    #pragma unroll
    for (int u = 0; u < 3; u++) {
        int p = u * 32 + lane;
        if (p < 68) {
            int h = p / 17, i1 = p - h * 17;
            const float* qv = qs + i1 * QS2 + h * 16;
            float s[17], smax = -1e30f;
            #pragma unroll
            for (int i2 = 0; i2 < 17; i2++) {
                const float* kv = ks + i2 * QS2 + h * 16;
                float d = 0.f;
                #pragma unroll
                for (int j = 0; j < 16; j++) d += qv[j] * kv[j];
                d *= 0.25f;
                s[i2] = d;
                smax = fmaxf(smax, d);
            }
            float den = 0.f, num = 0.f;
            #pragma unroll
            for (int i2 = 0; i2 < 17; i2++) {
                float e = __expf(s[i2] - smax);
                den += e;
                num += e * vss[i2 * 4 + h];
            }
            partial += num / den;
        }
    }
    #pragma unroll
    for (int off = 16; off; off >>= 1)
        partial += __shfl_down_sync(0xffffffffu, partial, off);
    if (lane == 0) out[row] = lrelu(partial * (1.f / 17.f) + g_const);
}

// ---------------------------------------------------------------------------
extern "C" void kernel_launch(void* const* d_in, const int* in_sizes, int n_in,
                              void* d_out, int out_size)
{
    const float* x   = (const float*)d_in[0];
    const float* W1  = (const float*)d_in[1];
    const float* b1  = (const float*)d_in[2];
    const float* Wm  = (const float*)d_in[3];
    const float* bm  = (const float*)d_in[4];
    const float* Wf  = (const float*)d_in[5];
    const float* bf  = (const float*)d_in[6];
    const float* Wq  = (const float*)d_in[7];
    const float* bq  = (const float*)d_in[8];
    const float* Wk  = (const float*)d_in[9];
    const float* bk  = (const float*)d_in[10];
    const float* Wv  = (const float*)d_in[11];
    const float* bv  = (const float*)d_in[12];
    const float* Wo  = (const float*)d_in[13];
    const float* bo  = (const float*)d_in[14];
    const float* Wfc = (const float*)d_in[15];
    const float* bfc = (const float*)d_in[16];
    float* out = (float*)d_out;

    const int k2_smem = 8 * (2 * Dn * QS2 + 68) * (int)sizeof(float);

    cudaFuncSetAttribute(subnet_mma_kernel, cudaFuncAttributeMaxDynamicSharedMemorySize, SM_TOTAL);
    cudaFuncSetAttribute(attn_kernel,       cudaFuncAttributeMaxDynamicSharedMemorySize, k2_smem);

    setup1_kernel<<<1, 64>>>(Wv, bv, Wo, bo, Wfc, bfc);
    setup2_kernel<<<Dn, 256>>>(Wf, bf, Wq, bq, Wk, bk);
    setup_midblob_kernel<<<2 * Dn * 8, 256>>>(Wm);
    setup_finblob_kernel<<<Dn * 2, 256>>>();

    dim3 g1(Bn / 128, Dn);
    subnet_mma_kernel<<<g1, 256, SM_TOTAL>>>(x, W1, b1, bm);

    attn_kernel<<<Bn / 8, 256, k2_smem>>>(out);
}

// round 14
// speedup vs baseline: 4.9541x; 1.0280x over previous
#include <cuda_runtime.h>
#include <cuda_fp16.h>
#include <cstdint>

#define SLOPE 0.01f
#define Dn 17
#define Hn 256
#define En 64
#define NCB 136
#define Bn 16384

// smem byte offsets (main kernel)
#define SM_X     0        // 128 floats
#define SM_W1    512      // 256 floats
#define SM_B1    1536     // 256 floats
#define SM_BM0   2560     // 256 floats
#define SM_BM1   3584     // 256 floats
#define SM_BC    4608     // 136 floats
#define SM_BBUF  5248     // 2 x 17408 B pair double-buffer (chunk slots at +0 / +8704)
#define SM_ANX   40064    // 8 warps x 16 slots x 32 lanes x 16B = 64KB (A-frag spill)
#define SM_TOTAL (40064 + 65536)

// ---- static device scratch (no allocation) ----
__device__ __half g_q [(size_t)Bn * Dn * En];   // fp16 q (halves attn DRAM traffic)
__device__ __half g_k [(size_t)Bn * Dn * En];   // fp16 k
__device__ float g_vs[(size_t)Bn * Dn * 4];
__device__ float g_Wcomb[Dn * Hn * NCB];
__device__ float g_bcomb[Dn * NCB];
__device__ float g_cv[4 * En];
__device__ float g_dv[4];
__device__ float g_const;
// fragment-ordered fp16 weight blobs; each uint4 = {hi.b0, hi.b1, lo.b0, lo.b1}
// mid: per mat (l*17+i): [h*16+kt][ntl][lane] -> 16384 uint4
__device__ uint4 g_Bmid[(size_t)2 * Dn * 16384];
// fin: per i: [kt][nt][lane] -> 8704 uint4
__device__ uint4 g_Bfin[(size_t)Dn * 8704];

__device__ __forceinline__ float lrelu(float v) { return v >= 0.f ? v : SLOPE * v; }

// pack two f32 -> f16x2 (first arg -> bits[15:0], second -> bits[31:16])
__device__ __forceinline__ uint32_t pkh(float lo, float hi) {
    uint32_t r;
    asm("cvt.rn.f16x2.f32 %0, %1, %2;" : "=r"(r) : "f"(hi), "f"(lo));
    return r;
}
__device__ __forceinline__ float f16res(float v) {
    return v - __half2float(__float2half_rn(v));
}

// fp32-accumulator MMA (hi pass)
__device__ __forceinline__ void mma16816(float* d, const uint32_t* a, uint32_t b0, uint32_t b1) {
    asm volatile(
        "mma.sync.aligned.m16n8k16.row.col.f32.f16.f16.f32 "
        "{%0,%1,%2,%3}, {%4,%5,%6,%7}, {%8,%9}, {%0,%1,%2,%3};"
        : "+f"(d[0]), "+f"(d[1]), "+f"(d[2]), "+f"(d[3])
        : "r"(a[0]), "r"(a[1]), "r"(a[2]), "r"(a[3]), "r"(b0), "r"(b1));
}
// fp16-accumulator MMA (lo pass; result is a tiny correction term)
__device__ __forceinline__ void mma16816h(uint32_t* d, const uint32_t* a, uint32_t b0, uint32_t b1) {
    asm volatile(
        "mma.sync.aligned.m16n8k16.row.col.f16.f16.f16.f16 "
        "{%0,%1}, {%2,%3,%4,%5}, {%6,%7}, {%0,%1};"
        : "+r"(d[0]), "+r"(d[1])
        : "r"(a[0]), "r"(a[1]), "r"(a[2]), "r"(a[3]), "r"(b0), "r"(b1));
}

__device__ __forceinline__ void cpa16(void* sdst, const void* gsrc) {
    uint32_t s = (uint32_t)__cvta_generic_to_shared(sdst);
    asm volatile("cp.async.cg.shared.global [%0], [%1], 16;" :: "r"(s), "l"(gsrc));
}
#define CPCOMMIT() asm volatile("cp.async.commit_group;")
#define CPWAIT(n)  asm volatile("cp.async.wait_group %0;" :: "n"(n))

// ============================ setup kernels ============================
__global__ void setup1_kernel(const float* __restrict__ Wv, const float* __restrict__ bv,
                              const float* __restrict__ Wo, const float* __restrict__ bo,
                              const float* __restrict__ Wfc, const float* __restrict__ bfc)
{
    __shared__ float us[64];
    int t = threadIdx.x;
    float s = 0.f;
    for (int e = 0; e < 64; e++) s += Wo[e * 64 + t] * Wfc[e];
    us[t] = s;
    __syncthreads();
    for (int h = 0; h < 4; h++) {
        float c = 0.f;
        for (int j = 0; j < 16; j++) c += Wv[(h * 16 + j) * 64 + t] * us[h * 16 + j];
        g_cv[h * 64 + t] = c;
    }
    if (t < 4) {
        float dsum = 0.f;
        for (int j = 0; j < 16; j++) dsum += bv[t * 16 + j] * us[t * 16 + j];
        g_dv[t] = dsum;
    }
    if (t == 0) {
        float c = bfc[0];
        for (int e = 0; e < 64; e++) c += bo[e] * Wfc[e];
        g_const = c;
    }
}

// merged: blocks 0..16 run setup2 (combined final-layer weights); blocks 17.. run midblob
__global__ void setup2_mid_kernel(const float* __restrict__ Wf, const float* __restrict__ bf,
                                  const float* __restrict__ Wq, const float* __restrict__ bq,
                                  const float* __restrict__ Wk, const float* __restrict__ bk,
                                  const float* __restrict__ Wm)
{
    __shared__ float Wqs[4096], Wks[4096], cvs[256];
    int t = threadIdx.x;
    if (blockIdx.x >= Dn) {
        // ---- midblob part ----
        int b = blockIdx.x - Dn;
        int mat = b >> 3, part = b & 7;
        const float* W = Wm + (size_t)mat * 65536;
        uint4* dst = g_Bmid + (size_t)mat * 16384;
        for (int idx = part * 2048 + t; idx < (part + 1) * 2048; idx += 256) {
            int lane = idx & 31;
            int ntl  = (idx >> 5) & 15;
            int kt   = (idx >> 9) & 15;
            int h    = (idx >> 13) & 1;
            int n  = (h * 16 + ntl) * 8 + (lane >> 2);
            int k0 = kt * 16 + (lane & 3) * 2;
            float w0 = W[(k0 + 0) * 256 + n], w1 = W[(k0 + 1) * 256 + n];
            float w8 = W[(k0 + 8) * 256 + n], w9 = W[(k0 + 9) * 256 + n];
            uint4 v;
            v.x = pkh(w0, w1);
            v.y = pkh(w8, w9);
            v.z = pkh(f16res(w0), f16res(w1));
            v.w = pkh(f16res(w8), f16res(w9));
            dst[idx] = v;
        }
        return;
    }

    // ---- setup2 part ----
    int i = blockIdx.x;
    #pragma unroll
    for (int u = 0; u < 16; u++) {
        int idx = t + 256 * u;
        Wqs[idx] = Wq[idx];
        Wks[idx] = Wk[idx];
    }
    cvs[t] = g_cv[t];
    __syncthreads();

    int k = t;
    float wf[64];
    #pragma unroll
    for (int tt = 0; tt < 64; tt++) wf[tt] = Wf[((size_t)i * 256 + k) * 64 + tt];
    float* dst = g_Wcomb + ((size_t)i * 256 + k) * NCB;
    for (int e = 0; e < 64; e++) {
        float sq = 0.f, sk = 0.f;
        #pragma unroll
        for (int tt = 0; tt < 64; tt++) { sq += wf[tt] * Wqs[e * 64 + tt]; sk += wf[tt] * Wks[e * 64 + tt]; }
        dst[e] = sq; dst[64 + e] = sk;
    }
    #pragma unroll
    for (int h = 0; h < 4; h++) {
        float sv = 0.f;
        #pragma unroll
        for (int tt = 0; tt < 64; tt++) sv += wf[tt] * cvs[h * 64 + tt];
        dst[128 + h] = sv;
    }
    dst[132] = dst[133] = dst[134] = dst[135] = 0.f;

    if (t < NCB) {
        float v;
        if (t < 64) {
            v = bq[t];
            for (int tt = 0; tt < 64; tt++) v += bf[i * 64 + tt] * Wqs[t * 64 + tt];
        } else if (t < 128) {
            int e = t - 64; v = bk[e];
            for (int tt = 0; tt < 64; tt++) v += bf[i * 64 + tt] * Wks[e * 64 + tt];
        } else if (t < 132) {
            int h = t - 128; v = g_dv[h];
            for (int tt = 0; tt < 64; tt++) v += bf[i * 64 + tt] * cvs[h * 64 + tt];
        } else v = 0.f;
        g_bcomb[i * NCB + t] = v;
    }
}

// final combined weights -> fp16 hi/lo fragment blobs. grid 17*2 blocks.
__global__ void setup_finblob_kernel()
{
    int i = blockIdx.x >> 1, part = blockIdx.x & 1;
    uint4* dst = g_Bfin + (size_t)i * 8704;
    int lo_i = part * 4352, hi_i = lo_i + 4352;
    const float* W = g_Wcomb + (size_t)i * 256 * NCB;
    for (int idx = lo_i + threadIdx.x; idx < hi_i; idx += 256) {
        int lane = idx & 31;
        int q  = idx >> 5;
        int nt = q % 17;
        int kt = q / 17;
        int n  = nt * 8 + (lane >> 2);
        int k0 = kt * 16 + (lane & 3) * 2;
        float w0 = W[(k0 + 0) * NCB + n], w1 = W[(k0 + 1) * NCB + n];
        float w8 = W[(k0 + 8) * NCB + n], w9 = W[(k0 + 9) * NCB + n];
        uint4 v;
        v.x = pkh(w0, w1);
        v.y = pkh(w8, w9);
        v.z = pkh(f16res(w0), f16res(w1));
        v.w = pkh(f16res(w8), f16res(w9));
        dst[idx] = v;
    }
}

// ============================ main kernel ============================
// pair p = two chunks staged into the two 8704B slots of buffer (p&1).
// mid chunks are 8192B (512 uint4); fin chunks are 8704B (544 uint4).
// Consumer always reads chunk `half` at byte offset half*8704.
__device__ __forceinline__ void stage_pair(char* smem, int p, int i, int t)
{
    char* dst = smem + SM_BBUF + (p & 1) * 17408;
    if (p < 32) {
        int layer = p >> 4, rem2 = p & 15;
        const char* src = (const char*)(g_Bmid + (size_t)(layer * Dn + i) * 16384 + (size_t)rem2 * 1024);
        #pragma unroll
        for (int u = 0; u < 2; u++) {
            int o = (t + u * 256) * 16;
            cpa16(dst + o,        src + o);
            cpa16(dst + 8704 + o, src + 8192 + o);
        }
    } else {
        const char* src = (const char*)(g_Bfin + (size_t)i * 8704 + (size_t)(p - 32) * 1088);
        #pragma unroll
        for (int u = 0; u < 5; u++) {
            int o = t + u * 256;
            if (o < 1088) cpa16(dst + o * 16, src + o * 16);
        }
    }
}

__global__ void __launch_bounds__(256, 1) subnet_mma_kernel(
    const float* __restrict__ x, const float* __restrict__ W1,
    const float* __restrict__ b1, const float* __restrict__ bm)
{
    extern __shared__ char smem[];
    float* xs   = (float*)(smem + SM_X);
    float* w1s  = (float*)(smem + SM_W1);
    float* b1s  = (float*)(smem + SM_B1);
    float* bm0s = (float*)(smem + SM_BM0);
    float* bm1s = (float*)(smem + SM_BM1);
    float* bcs  = (float*)(smem + SM_BC);

    const int t = threadIdx.x, w = t >> 5, lane = t & 31;
    const int gr = lane >> 2, c = lane & 3;
    const int i  = blockIdx.y, r0 = blockIdx.x * 128;

    // stage pair 0 ASAP
    stage_pair(smem, 0, i, t);
    CPCOMMIT();

    // stage constants
    if (t < 128) xs[t] = x[(size_t)(r0 + t) * Dn + i];
    w1s[t]  = W1[i * 256 + t];
    b1s[t]  = b1[i * 256 + t];
    bm0s[t] = bm[(0 * Dn + i) * 256 + t];
    bm1s[t] = bm[(1 * Dn + i) * 256 + t];
    if (t < NCB) bcs[t] = g_bcomb[i * NCB + t];
    __syncthreads();

    // ---- first layer: outer product -> A fragments (fp16, regs only) ----
    uint32_t Ahi[16][4];
    {
        float xa = xs[w * 16 + gr];
        float xb = xs[w * 16 + gr + 8];
        #pragma unroll
        for (int kt = 0; kt < 16; kt++) {
            int c0 = kt * 16 + 2 * c;
            float W0 = w1s[c0], W1v = w1s[c0 + 1], W8 = w1s[c0 + 8], W9 = w1s[c0 + 9];
            float B0 = b1s[c0], B1v = b1s[c0 + 1], B8 = b1s[c0 + 8], B9 = b1s[c0 + 9];
            Ahi[kt][0] = pkh(lrelu(fmaf(xa, W0, B0)), lrelu(fmaf(xa, W1v, B1v)));
            Ahi[kt][1] = pkh(lrelu(fmaf(xb, W0, B0)), lrelu(fmaf(xb, W1v, B1v)));
            Ahi[kt][2] = pkh(lrelu(fmaf(xa, W8, B8)), lrelu(fmaf(xa, W9, B9)));
            Ahi[kt][3] = pkh(lrelu(fmaf(xb, W8, B8)), lrelu(fmaf(xb, W9, B9)));
        }
    }

    // ---- two middle 256x256 layers ----
    #pragma unroll 1
    for (int layer = 0; layer < 2; layer++) {
        const float* bmls = (layer == 0) ? bm0s : bm1s;

        #pragma unroll
        for (int h = 0; h < 2; h++) {
            float acc[16][4];
            uint32_t accL[16][2];
            #pragma unroll
            for (int n_ = 0; n_ < 16; n_++) {
                #pragma unroll
                for (int r = 0; r < 4; r++) acc[n_][r] = 0.f;
                accL[n_][0] = 0u; accL[n_][1] = 0u;
            }

            #pragma unroll
            for (int ktp = 0; ktp < 8; ktp++) {
                const int p = layer * 16 + h * 8 + ktp;
                __syncthreads();   // consumers of pair p-1 done -> buffer (p+1)&1 free
                if (p < 39) { stage_pair(smem, p + 1, i, t); CPCOMMIT(); CPWAIT(1); }
                else        { CPWAIT(0); }
                __syncthreads();   // pair p fully staged for all threads

                const char* bb = smem + SM_BBUF + (p & 1) * 17408;
                #pragma unroll
                for (int half = 0; half < 2; half++) {
                    const char* bc2 = bb + half * 8704;
                    const int kt = 2 * ktp + half;
                    #pragma unroll
                    for (int ntl = 0; ntl < 16; ntl++) {
                        uint4 b4 = *(const uint4*)(bc2 + (ntl * 32 + lane) * 16);
                        mma16816 (acc [ntl], Ahi[kt], b4.x, b4.y);   // A * W_hi (f32 acc)
                        mma16816h(accL[ntl], Ahi[kt], b4.z, b4.w);   // A * W_lo (f16 acc)
                    }
                }
            }

            // epilogue: merge lo, bias + lrelu, pack -> smem A-frag slots (thread-private)
            #pragma unroll
            for (int j = 0; j < 8; j++) {
                int nt0 = 2 * j, nt1 = 2 * j + 1;
                int cb = 128 * h + 16 * j + 2 * c;
                float2 l00 = __half22float2(*(__half2*)&accL[nt0][0]);
                float2 l01 = __half22float2(*(__half2*)&accL[nt0][1]);
                float2 l10 = __half22float2(*(__half2*)&accL[nt1][0]);
                float2 l11 = __half22float2(*(__half2*)&accL[nt1][1]);
                float2 bb0 = *(const float2*)(bmls + cb);
                float2 bb1 = *(const float2*)(bmls + cb + 8);
                uint4 frag;
                frag.x = pkh(lrelu(acc[nt0][0] + l00.x + bb0.x), lrelu(acc[nt0][1] + l00.y + bb0.y));
                frag.y = pkh(lrelu(acc[nt0][2] + l01.x + bb0.x), lrelu(acc[nt0][3] + l01.y + bb0.y));
                frag.z = pkh(lrelu(acc[nt1][0] + l10.x + bb1.x), lrelu(acc[nt1][1] + l10.y + bb1.y));
                frag.w = pkh(lrelu(acc[nt1][2] + l11.x + bb1.x), lrelu(acc[nt1][3] + l11.y + bb1.y));
                *(uint4*)(smem + SM_ANX + (((w * 16) + 8 * h + j) * 32 + lane) * 16) = frag;
            }
        }

        // reload next-layer A-frags from thread-private smem slots (no sync needed)
        #pragma unroll
        for (int q = 0; q < 16; q++) {
            uint4 v = *(const uint4*)(smem + SM_ANX + ((w * 16 + q) * 32 + lane) * 16);
            Ahi[q][0] = v.x; Ahi[q][1] = v.y; Ahi[q][2] = v.z; Ahi[q][3] = v.w;
        }
    }

    // ---- final layer: 256 -> 136 (q | k | vs) ----
    {
        float fac[17][4];
        uint32_t facL[17][2];
        #pragma unroll
        for (int n_ = 0; n_ < 17; n_++) {
            #pragma unroll
            for (int r = 0; r < 4; r++) fac[n_][r] = 0.f;
            facL[n_][0] = 0u; facL[n_][1] = 0u;
        }

        #pragma unroll
        for (int ktp2 = 0; ktp2 < 8; ktp2++) {
            const int p = 32 + ktp2;
            __syncthreads();
            if (p < 39) { stage_pair(smem, p + 1, i, t); CPCOMMIT(); CPWAIT(1); }
            else        { CPWAIT(0); }
            __syncthreads();

            const char* bb = smem + SM_BBUF + (p & 1) * 17408;
            #pragma unroll
            for (int half = 0; half < 2; half++) {
                const char* bc2 = bb + half * 8704;
                const int kt = 2 * ktp2 + half;
                #pragma unroll
                for (int nt = 0; nt < 17; nt++) {
                    uint4 b4 = *(const uint4*)(bc2 + (nt * 32 + lane) * 16);
                    mma16816 (fac [nt], Ahi[kt], b4.x, b4.y);
                    mma16816h(facL[nt], Ahi[kt], b4.z, b4.w);
                }
            }
        }

        // epilogue: merge lo, bias + scatter; q/k stored as fp16
        const int row0 = r0 + w * 16 + gr, row1 = row0 + 8;
        #pragma unroll
        for (int nt = 0; nt < 17; nt++) {
            int col = nt * 8 + 2 * c;
            float2 l0 = __half22float2(*(__half2*)&facL[nt][0]);
            float2 l1 = __half22float2(*(__half2*)&facL[nt][1]);
            float2 bb = *(const float2*)(bcs + col);
            float o0x = fac[nt][0] + l0.x + bb.x, o0y = fac[nt][1] + l0.y + bb.y;
            float o1x = fac[nt][2] + l1.x + bb.x, o1y = fac[nt][3] + l1.y + bb.y;
            if (nt < 8) {
                *(uint32_t*)&g_q[((size_t)row0 * Dn + i) * En + col] = pkh(o0x, o0y);
                *(uint32_t*)&g_q[((size_t)row1 * Dn + i) * En + col] = pkh(o1x, o1y);
            } else if (nt < 16) {
                *(uint32_t*)&g_k[((size_t)row0 * Dn + i) * En + (col - 64)] = pkh(o0x, o0y);
                *(uint32_t*)&g_k[((size_t)row1 * Dn + i) * En + (col - 64)] = pkh(o1x, o1y);
            } else if (c < 2) {
                *(float2*)&g_vs[((size_t)row0 * Dn + i) * 4 + (col - 128)] = make_float2(o0x, o0y);
                *(float2*)&g_vs[((size_t)row1 * Dn + i) * 4 + (col - 128)] = make_float2(o1x, o1y);
            }
        }
    }
}

// ============================ attention-lite kernel ============================
#define QS2 68
__global__ void __launch_bounds__(256, 2) attn_kernel(float* __restrict__ out)
{
    extern __shared__ float smemf[];
    const int t = threadIdx.x, wid = t >> 5, lane = t & 31;
    float* qs  = smemf + wid * (2 * Dn * QS2 + 68);
    float* ks  = qs + Dn * QS2;
    float* vss = ks + Dn * QS2;

    const int row = blockIdx.x * 8 + wid;
    const uint32_t* qr = (const uint32_t*)(g_q + (size_t)row * (Dn * En));
    const uint32_t* kr = (const uint32_t*)(g_k + (size_t)row * (Dn * En));

    // 544 half2 pairs each for q and k
    #pragma unroll
    for (int u = 0; u < 17; u++) {
        int o = u * 32 + lane;             // half2 index 0..543
        int e2 = (o * 2) & 63;
        int ii = (o * 2) >> 6;
        float2 qf = __half22float2(*(const __half2*)&qr[o]);
        float2 kf = __half22float2(*(const __half2*)&kr[o]);
        qs[ii * QS2 + e2]     = qf.x;
        qs[ii * QS2 + e2 + 1] = qf.y;
        ks[ii * QS2 + e2]     = kf.x;
        ks[ii * QS2 + e2 + 1] = kf.y;
    }
    #pragma unroll
    for (int u = 0; u < 3; u++) {
        int p = u * 32 + lane;
        if (p < 68) vss[p] = g_vs[(size_t)row * 68 + p];
    }
    __syncwarp();

    float partial = 0.f;
    #pragma unroll
    for (int u = 0; u < 3; u++) {
        int p = u * 32 + lane;
        if (p < 68) {
            int h = p / 17, i1 = p - h * 17;
            const float* qv = qs + i1 * QS2 + h * 16;
            float s[17], smax = -1e30f;
            #pragma unroll
            for (int i2 = 0; i2 < 17; i2++) {
                const float* kv = ks + i2 * QS2 + h * 16;
                float d = 0.f;
                #pragma unroll
                for (int j = 0; j < 16; j++) d += qv[j] * kv[j];
                d *= 0.25f;
                s[i2] = d;
                smax = fmaxf(smax, d);
            }
            float den = 0.f, num = 0.f;
            #pragma unroll
            for (int i2 = 0; i2 < 17; i2++) {
                float e = __expf(s[i2] - smax);
                den += e;
                num += e * vss[i2 * 4 + h];
            }
            partial += num / den;
        }
    }
    #pragma unroll
    for (int off = 16; off; off >>= 1)
        partial += __shfl_down_sync(0xffffffffu, partial, off);
    if (lane == 0) out[row] = lrelu(partial * (1.f / 17.f) + g_const);
}

// ---------------------------------------------------------------------------
extern "C" void kernel_launch(void* const* d_in, const int* in_sizes, int n_in,
                              void* d_out, int out_size)
{
    const float* x   = (const float*)d_in[0];
    const float* W1  = (const float*)d_in[1];
    const float* b1  = (const float*)d_in[2];
    const float* Wm  = (const float*)d_in[3];
    const float* bm  = (const float*)d_in[4];
    const float* Wf  = (const float*)d_in[5];
    const float* bf  = (const float*)d_in[6];
    const float* Wq  = (const float*)d_in[7];
    const float* bq  = (const float*)d_in[8];
    const float* Wk  = (const float*)d_in[9];
    const float* bk  = (const float*)d_in[10];
    const float* Wv  = (const float*)d_in[11];
    const float* bv  = (const float*)d_in[12];
    const float* Wo  = (const float*)d_in[13];
    const float* bo  = (const float*)d_in[14];
    const float* Wfc = (const float*)d_in[15];
    const float* bfc = (const float*)d_in[16];
    float* out = (float*)d_out;

    const int k2_smem = 8 * (2 * Dn * QS2 + 68) * (int)sizeof(float);

    cudaFuncSetAttribute(subnet_mma_kernel, cudaFuncAttributeMaxDynamicSharedMemorySize, SM_TOTAL);
    cudaFuncSetAttribute(attn_kernel,       cudaFuncAttributeMaxDynamicSharedMemorySize, k2_smem);

    setup1_kernel<<<1, 64>>>(Wv, bv, Wo, bo, Wfc, bfc);
    setup2_mid_kernel<<<Dn + 2 * Dn * 8, 256>>>(Wf, bf, Wq, bq, Wk, bk, Wm);
    setup_finblob_kernel<<<Dn * 2, 256>>>();

    dim3 g1(Bn / 128, Dn);
    subnet_mma_kernel<<<g1, 256, SM_TOTAL>>>(x, W1, b1, bm);

    attn_kernel<<<Bn / 8, 256, k2_smem>>>(out);
}

// round 16
// speedup vs baseline: 4.9963x; 1.0085x over previous
#include <cuda_runtime.h>
#include <cuda_fp16.h>
#include <cstdint>

#define SLOPE 0.01f
#define Dn 17
#define Hn 256
#define En 64
#define NCB 136
#define Bn 16384

// smem byte offsets (main kernel, 4-warp CTA)
#define SM_X     0        // 64 floats
#define SM_W1    512      // 256 floats
#define SM_B1    1536     // 256 floats
#define SM_BM0   2560     // 256 floats
#define SM_BM1   3584     // 256 floats
#define SM_BC    4608     // 136 floats
#define SM_BBUF  5248     // 2 x 17408 B pair double-buffer (chunk slots at +0 / +8704)
#define SM_ANX   40064    // 4 warps x 16 slots x 32 lanes x 16B = 32KB (A-frag spill)
#define SM_TOTAL (40064 + 32768)

// ---- static device scratch (no allocation) ----
__device__ __half g_q [(size_t)Bn * Dn * En];   // fp16 q (halves attn DRAM traffic)
__device__ __half g_k [(size_t)Bn * Dn * En];   // fp16 k
__device__ float g_vs[(size_t)Bn * Dn * 4];
__device__ float g_Wcomb[Dn * Hn * NCB];
__device__ float g_bcomb[Dn * NCB];
__device__ float g_cv[4 * En];
__device__ float g_dv[4];
__device__ float g_const;
// fragment-ordered fp16 weight blobs; each uint4 = {hi.b0, hi.b1, lo.b0, lo.b1}
__device__ uint4 g_Bmid[(size_t)2 * Dn * 16384];
__device__ uint4 g_Bfin[(size_t)Dn * 8704];

__device__ __forceinline__ float lrelu(float v) { return v >= 0.f ? v : SLOPE * v; }

__device__ __forceinline__ uint32_t pkh(float lo, float hi) {
    uint32_t r;
    asm("cvt.rn.f16x2.f32 %0, %1, %2;" : "=r"(r) : "f"(hi), "f"(lo));
    return r;
}
__device__ __forceinline__ float f16res(float v) {
    return v - __half2float(__float2half_rn(v));
}

__device__ __forceinline__ void mma16816(float* d, const uint32_t* a, uint32_t b0, uint32_t b1) {
    asm volatile(
        "mma.sync.aligned.m16n8k16.row.col.f32.f16.f16.f32 "
        "{%0,%1,%2,%3}, {%4,%5,%6,%7}, {%8,%9}, {%0,%1,%2,%3};"
        : "+f"(d[0]), "+f"(d[1]), "+f"(d[2]), "+f"(d[3])
        : "r"(a[0]), "r"(a[1]), "r"(a[2]), "r"(a[3]), "r"(b0), "r"(b1));
}
__device__ __forceinline__ void mma16816h(uint32_t* d, const uint32_t* a, uint32_t b0, uint32_t b1) {
    asm volatile(
        "mma.sync.aligned.m16n8k16.row.col.f16.f16.f16.f16 "
        "{%0,%1}, {%2,%3,%4,%5}, {%6,%7}, {%0,%1};"
        : "+r"(d[0]), "+r"(d[1])
        : "r"(a[0]), "r"(a[1]), "r"(a[2]), "r"(a[3]), "r"(b0), "r"(b1));
}

__device__ __forceinline__ void cpa16(void* sdst, const void* gsrc) {
    uint32_t s = (uint32_t)__cvta_generic_to_shared(sdst);
    asm volatile("cp.async.cg.shared.global [%0], [%1], 16;" :: "r"(s), "l"(gsrc));
}
#define CPCOMMIT() asm volatile("cp.async.commit_group;")
#define CPWAIT(n)  asm volatile("cp.async.wait_group %0;" :: "n"(n))

// ============================ setup kernels ============================
__global__ void setup1_kernel(const float* __restrict__ Wv, const float* __restrict__ bv,
                              const float* __restrict__ Wo, const float* __restrict__ bo,
                              const float* __restrict__ Wfc, const float* __restrict__ bfc)
{
    __shared__ float us[64];
    int t = threadIdx.x;
    float s = 0.f;
    for (int e = 0; e < 64; e++) s += Wo[e * 64 + t] * Wfc[e];
    us[t] = s;
    __syncthreads();
    for (int h = 0; h < 4; h++) {
        float c = 0.f;
        for (int j = 0; j < 16; j++) c += Wv[(h * 16 + j) * 64 + t] * us[h * 16 + j];
        g_cv[h * 64 + t] = c;
    }
    if (t < 4) {
        float dsum = 0.f;
        for (int j = 0; j < 16; j++) dsum += bv[t * 16 + j] * us[t * 16 + j];
        g_dv[t] = dsum;
    }
    if (t == 0) {
        float c = bfc[0];
        for (int e = 0; e < 64; e++) c += bo[e] * Wfc[e];
        g_const = c;
    }
}

// merged: blocks 0..16 run setup2 (combined final-layer weights); blocks 17.. run midblob
__global__ void setup2_mid_kernel(const float* __restrict__ Wf, const float* __restrict__ bf,
                                  const float* __restrict__ Wq, const float* __restrict__ bq,
                                  const float* __restrict__ Wk, const float* __restrict__ bk,
                                  const float* __restrict__ Wm)
{
    __shared__ float Wqs[4096], Wks[4096], cvs[256];
    int t = threadIdx.x;
    if (blockIdx.x >= Dn) {
        int b = blockIdx.x - Dn;
        int mat = b >> 3, part = b & 7;
        const float* W = Wm + (size_t)mat * 65536;
        uint4* dst = g_Bmid + (size_t)mat * 16384;
        for (int idx = part * 2048 + t; idx < (part + 1) * 2048; idx += 256) {
            int lane = idx & 31;
            int ntl  = (idx >> 5) & 15;
            int kt   = (idx >> 9) & 15;
            int h    = (idx >> 13) & 1;
            int n  = (h * 16 + ntl) * 8 + (lane >> 2);
            int k0 = kt * 16 + (lane & 3) * 2;
            float w0 = W[(k0 + 0) * 256 + n], w1 = W[(k0 + 1) * 256 + n];
            float w8 = W[(k0 + 8) * 256 + n], w9 = W[(k0 + 9) * 256 + n];
            uint4 v;
            v.x = pkh(w0, w1);
            v.y = pkh(w8, w9);
            v.z = pkh(f16res(w0), f16res(w1));
            v.w = pkh(f16res(w8), f16res(w9));
            dst[idx] = v;
        }
        return;
    }

    int i = blockIdx.x;
    #pragma unroll
    for (int u = 0; u < 16; u++) {
        int idx = t + 256 * u;
        Wqs[idx] = Wq[idx];
        Wks[idx] = Wk[idx];
    }
    cvs[t] = g_cv[t];
    __syncthreads();

    int k = t;
    float wf[64];
    #pragma unroll
    for (int tt = 0; tt < 64; tt++) wf[tt] = Wf[((size_t)i * 256 + k) * 64 + tt];
    float* dst = g_Wcomb + ((size_t)i * 256 + k) * NCB;
    for (int e = 0; e < 64; e++) {
        float sq = 0.f, sk = 0.f;
        #pragma unroll
        for (int tt = 0; tt < 64; tt++) { sq += wf[tt] * Wqs[e * 64 + tt]; sk += wf[tt] * Wks[e * 64 + tt]; }
        dst[e] = sq; dst[64 + e] = sk;
    }
    #pragma unroll
    for (int h = 0; h < 4; h++) {
        float sv = 0.f;
        #pragma unroll
        for (int tt = 0; tt < 64; tt++) sv += wf[tt] * cvs[h * 64 + tt];
        dst[128 + h] = sv;
    }
    dst[132] = dst[133] = dst[134] = dst[135] = 0.f;

    if (t < NCB) {
        float v;
        if (t < 64) {
            v = bq[t];
            for (int tt = 0; tt < 64; tt++) v += bf[i * 64 + tt] * Wqs[t * 64 + tt];
        } else if (t < 128) {
            int e = t - 64; v = bk[e];
            for (int tt = 0; tt < 64; tt++) v += bf[i * 64 + tt] * Wks[e * 64 + tt];
        } else if (t < 132) {
            int h = t - 128; v = g_dv[h];
            for (int tt = 0; tt < 64; tt++) v += bf[i * 64 + tt] * cvs[h * 64 + tt];
        } else v = 0.f;
        g_bcomb[i * NCB + t] = v;
    }
}

__global__ void setup_finblob_kernel()
{
    int i = blockIdx.x >> 1, part = blockIdx.x & 1;
    uint4* dst = g_Bfin + (size_t)i * 8704;
    int lo_i = part * 4352, hi_i = lo_i + 4352;
    const float* W = g_Wcomb + (size_t)i * 256 * NCB;
    for (int idx = lo_i + threadIdx.x; idx < hi_i; idx += 256) {
        int lane = idx & 31;
        int q  = idx >> 5;
        int nt = q % 17;
        int kt = q / 17;
        int n  = nt * 8 + (lane >> 2);
        int k0 = kt * 16 + (lane & 3) * 2;
        float w0 = W[(k0 + 0) * NCB + n], w1 = W[(k0 + 1) * NCB + n];
        float w8 = W[(k0 + 8) * NCB + n], w9 = W[(k0 + 9) * NCB + n];
        uint4 v;
        v.x = pkh(w0, w1);
        v.y = pkh(w8, w9);
        v.z = pkh(f16res(w0), f16res(w1));
        v.w = pkh(f16res(w8), f16res(w9));
        dst[idx] = v;
    }
}

// ============================ main kernel (4 warps, M=64, 2 CTAs/SM) ============================
// pair p = two chunks staged into the two 8704B slots of buffer (p&1). 128 threads.
__device__ __forceinline__ void stage_pair(char* smem, int p, int i, int t)
{
    char* dst = smem + SM_BBUF + (p & 1) * 17408;
    if (p < 32) {
        int layer = p >> 4, rem2 = p & 15;
        const char* src = (const char*)(g_Bmid + (size_t)(layer * Dn + i) * 16384 + (size_t)rem2 * 1024);
        #pragma unroll
        for (int u = 0; u < 4; u++) {
            int o = (t + u * 128) * 16;
            cpa16(dst + o,        src + o);
            cpa16(dst + 8704 + o, src + 8192 + o);
        }
    } else {
        const char* src = (const char*)(g_Bfin + (size_t)i * 8704 + (size_t)(p - 32) * 1088);
        #pragma unroll
        for (int u = 0; u < 9; u++) {
            int o = t + u * 128;
            if (o < 1088) cpa16(dst + o * 16, src + o * 16);
        }
    }
}

__global__ void __launch_bounds__(128, 2) subnet_mma_kernel(
    const float* __restrict__ x, const float* __restrict__ W1,
    const float* __restrict__ b1, const float* __restrict__ bm)
{
    extern __shared__ char smem[];
    float* xs   = (float*)(smem + SM_X);
    float* w1s  = (float*)(smem + SM_W1);
    float* b1s  = (float*)(smem + SM_B1);
    float* bm0s = (float*)(smem + SM_BM0);
    float* bm1s = (float*)(smem + SM_BM1);
    float* bcs  = (float*)(smem + SM_BC);

    const int t = threadIdx.x, w = t >> 5, lane = t & 31;
    const int gr = lane >> 2, c = lane & 3;
    const int i  = blockIdx.y, r0 = blockIdx.x * 64;

    // stage pair 0 ASAP
    stage_pair(smem, 0, i, t);
    CPCOMMIT();

    // stage constants (128-thread strides everywhere — NCB=136 needs a loop!)
    if (t < 64) xs[t] = x[(size_t)(r0 + t) * Dn + i];
    for (int idx = t; idx < 256; idx += 128) {
        w1s[idx]  = W1[i * 256 + idx];
        b1s[idx]  = b1[i * 256 + idx];
        bm0s[idx] = bm[(0 * Dn + i) * 256 + idx];
        bm1s[idx] = bm[(1 * Dn + i) * 256 + idx];
    }
    for (int idx = t; idx < NCB; idx += 128) bcs[idx] = g_bcomb[i * NCB + idx];
    __syncthreads();

    // ---- first layer: outer product -> A fragments (fp16, regs only) ----
    uint32_t Ahi[16][4];
    {
        float xa = xs[w * 16 + gr];
        float xb = xs[w * 16 + gr + 8];
        #pragma unroll
        for (int kt = 0; kt < 16; kt++) {
            int c0 = kt * 16 + 2 * c;
            float W0 = w1s[c0], W1v = w1s[c0 + 1], W8 = w1s[c0 + 8], W9 = w1s[c0 + 9];
            float B0 = b1s[c0], B1v = b1s[c0 + 1], B8 = b1s[c0 + 8], B9 = b1s[c0 + 9];
            Ahi[kt][0] = pkh(lrelu(fmaf(xa, W0, B0)), lrelu(fmaf(xa, W1v, B1v)));
            Ahi[kt][1] = pkh(lrelu(fmaf(xb, W0, B0)), lrelu(fmaf(xb, W1v, B1v)));
            Ahi[kt][2] = pkh(lrelu(fmaf(xa, W8, B8)), lrelu(fmaf(xa, W9, B9)));
            Ahi[kt][3] = pkh(lrelu(fmaf(xb, W8, B8)), lrelu(fmaf(xb, W9, B9)));
        }
    }

    // ---- two middle 256x256 layers ----
    #pragma unroll 1
    for (int layer = 0; layer < 2; layer++) {
        const float* bmls = (layer == 0) ? bm0s : bm1s;

        #pragma unroll
        for (int h = 0; h < 2; h++) {
            float acc[16][4];
            uint32_t accL[16][2];
            #pragma unroll
            for (int n_ = 0; n_ < 16; n_++) {
                #pragma unroll
                for (int r = 0; r < 4; r++) acc[n_][r] = 0.f;
                accL[n_][0] = 0u; accL[n_][1] = 0u;
            }

            #pragma unroll
            for (int ktp = 0; ktp < 8; ktp++) {
                const int p = layer * 16 + h * 8 + ktp;
                __syncthreads();   // consumers of pair p-1 done -> buffer (p+1)&1 free
                if (p < 39) { stage_pair(smem, p + 1, i, t); CPCOMMIT(); CPWAIT(1); }
                else        { CPWAIT(0); }
                __syncthreads();   // pair p fully staged for all threads

                const char* bb = smem + SM_BBUF + (p & 1) * 17408;
                #pragma unroll
                for (int half = 0; half < 2; half++) {
                    const char* bc2 = bb + half * 8704;
                    const int kt = 2 * ktp + half;
                    #pragma unroll
                    for (int ntl = 0; ntl < 16; ntl++) {
                        uint4 b4 = *(const uint4*)(bc2 + (ntl * 32 + lane) * 16);
                        mma16816 (acc [ntl], Ahi[kt], b4.x, b4.y);   // A * W_hi (f32 acc)
                        mma16816h(accL[ntl], Ahi[kt], b4.z, b4.w);   // A * W_lo (f16 acc)
                    }
                }
            }

            // epilogue: merge lo, bias + lrelu, pack -> smem A-frag slots (thread-private)
            #pragma unroll
            for (int j = 0; j < 8; j++) {
                int nt0 = 2 * j, nt1 = 2 * j + 1;
                int cb = 128 * h + 16 * j + 2 * c;
                float2 l00 = __half22float2(*(__half2*)&accL[nt0][0]);
                float2 l01 = __half22float2(*(__half2*)&accL[nt0][1]);
                float2 l10 = __half22float2(*(__half2*)&accL[nt1][0]);
                float2 l11 = __half22float2(*(__half2*)&accL[nt1][1]);
                float2 bb0 = *(const float2*)(bmls + cb);
                float2 bb1 = *(const float2*)(bmls + cb + 8);
                uint4 frag;
                frag.x = pkh(lrelu(acc[nt0][0] + l00.x + bb0.x), lrelu(acc[nt0][1] + l00.y + bb0.y));
                frag.y = pkh(lrelu(acc[nt0][2] + l01.x + bb0.x), lrelu(acc[nt0][3] + l01.y + bb0.y));
                frag.z = pkh(lrelu(acc[nt1][0] + l10.x + bb1.x), lrelu(acc[nt1][1] + l10.y + bb1.y));
                frag.w = pkh(lrelu(acc[nt1][2] + l11.x + bb1.x), lrelu(acc[nt1][3] + l11.y + bb1.y));
                *(uint4*)(smem + SM_ANX + (((w * 16) + 8 * h + j) * 32 + lane) * 16) = frag;
            }
        }

        // reload next-layer A-frags from thread-private smem slots (no sync needed)
        #pragma unroll
        for (int q = 0; q < 16; q++) {
            uint4 v = *(const uint4*)(smem + SM_ANX + ((w * 16 + q) * 32 + lane) * 16);
            Ahi[q][0] = v.x; Ahi[q][1] = v.y; Ahi[q][2] = v.z; Ahi[q][3] = v.w;
        }
    }

    // ---- final layer: 256 -> 136 (q | k | vs) ----
    {
        float fac[17][4];
        uint32_t facL[17][2];
        #pragma unroll
        for (int n_ = 0; n_ < 17; n_++) {
            #pragma unroll
            for (int r = 0; r < 4; r++) fac[n_][r] = 0.f;
            facL[n_][0] = 0u; facL[n_][1] = 0u;
        }

        #pragma unroll
        for (int ktp2 = 0; ktp2 < 8; ktp2++) {
            const int p = 32 + ktp2;
            __syncthreads();
            if (p < 39) { stage_pair(smem, p + 1, i, t); CPCOMMIT(); CPWAIT(1); }
            else        { CPWAIT(0); }
            __syncthreads();

            const char* bb = smem + SM_BBUF + (p & 1) * 17408;
            #pragma unroll
            for (int half = 0; half < 2; half++) {
                const char* bc2 = bb + half * 8704;
                const int kt = 2 * ktp2 + half;
                #pragma unroll
                for (int nt = 0; nt < 17; nt++) {
                    uint4 b4 = *(const uint4*)(bc2 + (nt * 32 + lane) * 16);
                    mma16816 (fac [nt], Ahi[kt], b4.x, b4.y);
                    mma16816h(facL[nt], Ahi[kt], b4.z, b4.w);
                }
            }
        }

        // epilogue: merge lo, bias + scatter; q/k stored as fp16
        const int row0 = r0 + w * 16 + gr, row1 = row0 + 8;
        #pragma unroll
        for (int nt = 0; nt < 17; nt++) {
            int col = nt * 8 + 2 * c;
            float2 l0 = __half22float2(*(__half2*)&facL[nt][0]);
            float2 l1 = __half22float2(*(__half2*)&facL[nt][1]);
            float2 bb = *(const float2*)(bcs + col);
            float o0x = fac[nt][0] + l0.x + bb.x, o0y = fac[nt][1] + l0.y + bb.y;
            float o1x = fac[nt][2] + l1.x + bb.x, o1y = fac[nt][3] + l1.y + bb.y;
            if (nt < 8) {
                *(uint32_t*)&g_q[((size_t)row0 * Dn + i) * En + col] = pkh(o0x, o0y);
                *(uint32_t*)&g_q[((size_t)row1 * Dn + i) * En + col] = pkh(o1x, o1y);
            } else if (nt < 16) {
                *(uint32_t*)&g_k[((size_t)row0 * Dn + i) * En + (col - 64)] = pkh(o0x, o0y);
                *(uint32_t*)&g_k[((size_t)row1 * Dn + i) * En + (col - 64)] = pkh(o1x, o1y);
            } else if (c < 2) {
                *(float2*)&g_vs[((size_t)row0 * Dn + i) * 4 + (col - 128)] = make_float2(o0x, o0y);
                *(float2*)&g_vs[((size_t)row1 * Dn + i) * 4 + (col - 128)] = make_float2(o1x, o1y);
            }
        }
    }
}

// ============================ attention-lite kernel ============================
#define QS2 68
__global__ void __launch_bounds__(256, 2) attn_kernel(float* __restrict__ out)
{
    extern __shared__ float smemf[];
    const int t = threadIdx.x, wid = t >> 5, lane = t & 31;
    float* qs  = smemf + wid * (2 * Dn * QS2 + 68);
    float* ks  = qs + Dn * QS2;
    float* vss = ks + Dn * QS2;

    const int row = blockIdx.x * 8 + wid;
    const uint32_t* qr = (const uint32_t*)(g_q + (size_t)row * (Dn * En));
    const uint32_t* kr = (const uint32_t*)(g_k + (size_t)row * (Dn * En));

    #pragma unroll
    for (int u = 0; u < 17; u++) {
        int o = u * 32 + lane;             // half2 index 0..543
        int e2 = (o * 2) & 63;
        int ii = (o * 2) >> 6;
        float2 qf = __half22float2(*(const __half2*)&qr[o]);
        float2 kf = __half22float2(*(const __half2*)&kr[o]);
        qs[ii * QS2 + e2]     = qf.x;
        qs[ii * QS2 + e2 + 1] = qf.y;
        ks[ii * QS2 + e2]     = kf.x;
        ks[ii * QS2 + e2 + 1] = kf.y;
    }
    #pragma unroll
    for (int u = 0; u < 3; u++) {
        int p = u * 32 + lane;
        if (p < 68) vss[p] = g_vs[(size_t)row * 68 + p];
    }
    __syncwarp();

    float partial = 0.f;
    #pragma unroll
    for (int u = 0; u < 3; u++) {
        int p = u * 32 + lane;
        if (p < 68) {
            int h = p / 17, i1 = p - h * 17;
            const float* qv = qs + i1 * QS2 + h * 16;
            float s[17], smax = -1e30f;
            #pragma unroll
            for (int i2 = 0; i2 < 17; i2++) {
                const float* kv = ks + i2 * QS2 + h * 16;
                float d = 0.f;
                #pragma unroll
                for (int j = 0; j < 16; j++) d += qv[j] * kv[j];
                d *= 0.25f;
                s[i2] = d;
                smax = fmaxf(smax, d);
            }
            float den = 0.f, num = 0.f;
            #pragma unroll
            for (int i2 = 0; i2 < 17; i2++) {
                float e = __expf(s[i2] - smax);
                den += e;
                num += e * vss[i2 * 4 + h];
            }
            partial += num / den;
        }
    }
    #pragma unroll
    for (int off = 16; off; off >>= 1)
        partial += __shfl_down_sync(0xffffffffu, partial, off);
    if (lane == 0) out[row] = lrelu(partial * (1.f / 17.f) + g_const);
}

// ---------------------------------------------------------------------------
extern "C" void kernel_launch(void* const* d_in, const int* in_sizes, int n_in,
                              void* d_out, int out_size)
{
    const float* x   = (const float*)d_in[0];
    const float* W1  = (const float*)d_in[1];
    const float* b1  = (const float*)d_in[2];
    const float* Wm  = (const float*)d_in[3];
    const float* bm  = (const float*)d_in[4];
    const float* Wf  = (const float*)d_in[5];
    const float* bf  = (const float*)d_in[6];
    const float* Wq  = (const float*)d_in[7];
    const float* bq  = (const float*)d_in[8];
    const float* Wk  = (const float*)d_in[9];
    const float* bk  = (const float*)d_in[10];
    const float* Wv  = (const float*)d_in[11];
    const float* bv  = (const float*)d_in[12];
    const float* Wo  = (const float*)d_in[13];
    const float* bo  = (const float*)d_in[14];
    const float* Wfc = (const float*)d_in[15];
    const float* bfc = (const float*)d_in[16];
    float* out = (float*)d_out;

    const int k2_smem = 8 * (2 * Dn * QS2 + 68) * (int)sizeof(float);

    cudaFuncSetAttribute(subnet_mma_kernel, cudaFuncAttributeMaxDynamicSharedMemorySize, SM_TOTAL);
    cudaFuncSetAttribute(attn_kernel,       cudaFuncAttributeMaxDynamicSharedMemorySize, k2_smem);

    setup1_kernel<<<1, 64>>>(Wv, bv, Wo, bo, Wfc, bfc);
    setup2_mid_kernel<<<Dn + 2 * Dn * 8, 256>>>(Wf, bf, Wq, bq, Wk, bk, Wm);
    setup_finblob_kernel<<<Dn * 2, 256>>>();

    dim3 g1(Bn / 64, Dn);
    subnet_mma_kernel<<<g1, 128, SM_TOTAL>>>(x, W1, b1, bm);

    attn_kernel<<<Bn / 8, 256, k2_smem>>>(out);
}

// round 17
// speedup vs baseline: 7.4316x; 1.4874x over previous
#include <cuda_runtime.h>
#include <cuda_fp16.h>
#include <cstdint>

#define SLOPE 0.01f
#define Dn 17
#define Hn 256
#define En 64
#define NCB 136
#define Bn 16384

// smem byte offsets (main kernel, 4-warp CTA, single-pass fp16 weights)
#define SM_X     0        // 64 floats
#define SM_W1    512      // 256 floats
#define SM_B1    1536     // 256 floats
#define SM_BM0   2560     // 256 floats
#define SM_BM1   3584     // 256 floats
#define SM_BC    4608     // 136 floats
#define SM_BBUF  5248     // 2 x 8704 B pair double-buffer (chunk slots at +0 / +4352)
#define SM_ANX   22656    // 4 warps x 16 slots x 32 lanes x 16B = 32KB (A-frag spill)
#define SM_TOTAL (22656 + 32768)

// ---- static device scratch (no allocation) ----
__device__ __half g_q [(size_t)Bn * Dn * En];   // fp16 q (halves attn DRAM traffic)
__device__ __half g_k [(size_t)Bn * Dn * En];   // fp16 k
__device__ float g_vs[(size_t)Bn * Dn * 4];
__device__ float g_Wcomb[Dn * Hn * NCB];
__device__ float g_bcomb[Dn * NCB];
__device__ float g_cv[4 * En];
__device__ float g_dv[4];
__device__ float g_const;
// fragment-ordered fp16 weight blobs; each uint2 = {b0, b1} (single fp16 pass)
// mid: per mat (l*17+i): [h*16+kt][ntl][lane] -> 16384 uint2 (32 chunks x 512)
__device__ uint2 g_Bmid[(size_t)2 * Dn * 16384];
// fin: per i: [kt][nt][lane] -> 8704 uint2 (16 chunks x 544)
__device__ uint2 g_Bfin[(size_t)Dn * 8704];

__device__ __forceinline__ float lrelu(float v) { return v >= 0.f ? v : SLOPE * v; }

__device__ __forceinline__ uint32_t pkh(float lo, float hi) {
    uint32_t r;
    asm("cvt.rn.f16x2.f32 %0, %1, %2;" : "=r"(r) : "f"(hi), "f"(lo));
    return r;
}

__device__ __forceinline__ void mma16816(float* d, const uint32_t* a, uint32_t b0, uint32_t b1) {
    asm volatile(
        "mma.sync.aligned.m16n8k16.row.col.f32.f16.f16.f32 "
        "{%0,%1,%2,%3}, {%4,%5,%6,%7}, {%8,%9}, {%0,%1,%2,%3};"
        : "+f"(d[0]), "+f"(d[1]), "+f"(d[2]), "+f"(d[3])
        : "r"(a[0]), "r"(a[1]), "r"(a[2]), "r"(a[3]), "r"(b0), "r"(b1));
}

__device__ __forceinline__ void cpa16(void* sdst, const void* gsrc) {
    uint32_t s = (uint32_t)__cvta_generic_to_shared(sdst);
    asm volatile("cp.async.cg.shared.global [%0], [%1], 16;" :: "r"(s), "l"(gsrc));
}
#define CPCOMMIT() asm volatile("cp.async.commit_group;")
#define CPWAIT(n)  asm volatile("cp.async.wait_group %0;" :: "n"(n))

// ============================ setup kernels ============================
__global__ void setup1_kernel(const float* __restrict__ Wv, const float* __restrict__ bv,
                              const float* __restrict__ Wo, const float* __restrict__ bo,
                              const float* __restrict__ Wfc, const float* __restrict__ bfc)
{
    __shared__ float us[64];
    int t = threadIdx.x;
    float s = 0.f;
    for (int e = 0; e < 64; e++) s += Wo[e * 64 + t] * Wfc[e];
    us[t] = s;
    __syncthreads();
    for (int h = 0; h < 4; h++) {
        float c = 0.f;
        for (int j = 0; j < 16; j++) c += Wv[(h * 16 + j) * 64 + t] * us[h * 16 + j];
        g_cv[h * 64 + t] = c;
    }
    if (t < 4) {
        float dsum = 0.f;
        for (int j = 0; j < 16; j++) dsum += bv[t * 16 + j] * us[t * 16 + j];
        g_dv[t] = dsum;
    }
    if (t == 0) {
        float c = bfc[0];
        for (int e = 0; e < 64; e++) c += bo[e] * Wfc[e];
        g_const = c;
    }
}

// merged: blocks 0..16 run setup2; blocks 17.. run midblob
__global__ void setup2_mid_kernel(const float* __restrict__ Wf, const float* __restrict__ bf,
                                  const float* __restrict__ Wq, const float* __restrict__ bq,
                                  const float* __restrict__ Wk, const float* __restrict__ bk,
                                  const float* __restrict__ Wm)
{
    __shared__ float Wqs[4096], Wks[4096], cvs[256];
    int t = threadIdx.x;
    if (blockIdx.x >= Dn) {
        int b = blockIdx.x - Dn;
        int mat = b >> 3, part = b & 7;
        const float* W = Wm + (size_t)mat * 65536;
        uint2* dst = g_Bmid + (size_t)mat * 16384;
        for (int idx = part * 2048 + t; idx < (part + 1) * 2048; idx += 256) {
            int lane = idx & 31;
            int ntl  = (idx >> 5) & 15;
            int kt   = (idx >> 9) & 15;
            int h    = (idx >> 13) & 1;
            int n  = (h * 16 + ntl) * 8 + (lane >> 2);
            int k0 = kt * 16 + (lane & 3) * 2;
            float w0 = W[(k0 + 0) * 256 + n], w1 = W[(k0 + 1) * 256 + n];
            float w8 = W[(k0 + 8) * 256 + n], w9 = W[(k0 + 9) * 256 + n];
            dst[idx] = make_uint2(pkh(w0, w1), pkh(w8, w9));
        }
        return;
    }

    int i = blockIdx.x;
    #pragma unroll
    for (int u = 0; u < 16; u++) {
        int idx = t + 256 * u;
        Wqs[idx] = Wq[idx];
        Wks[idx] = Wk[idx];
    }
    cvs[t] = g_cv[t];
    __syncthreads();

    int k = t;
    float wf[64];
    #pragma unroll
    for (int tt = 0; tt < 64; tt++) wf[tt] = Wf[((size_t)i * 256 + k) * 64 + tt];
    float* dst = g_Wcomb + ((size_t)i * 256 + k) * NCB;
    for (int e = 0; e < 64; e++) {
        float sq = 0.f, sk = 0.f;
        #pragma unroll
        for (int tt = 0; tt < 64; tt++) { sq += wf[tt] * Wqs[e * 64 + tt]; sk += wf[tt] * Wks[e * 64 + tt]; }
        dst[e] = sq; dst[64 + e] = sk;
    }
    #pragma unroll
    for (int h = 0; h < 4; h++) {
        float sv = 0.f;
        #pragma unroll
        for (int tt = 0; tt < 64; tt++) sv += wf[tt] * cvs[h * 64 + tt];
        dst[128 + h] = sv;
    }
    dst[132] = dst[133] = dst[134] = dst[135] = 0.f;

    if (t < NCB) {
        float v;
        if (t < 64) {
            v = bq[t];
            for (int tt = 0; tt < 64; tt++) v += bf[i * 64 + tt] * Wqs[t * 64 + tt];
        } else if (t < 128) {
            int e = t - 64; v = bk[e];
            for (int tt = 0; tt < 64; tt++) v += bf[i * 64 + tt] * Wks[e * 64 + tt];
        } else if (t < 132) {
            int h = t - 128; v = g_dv[h];
            for (int tt = 0; tt < 64; tt++) v += bf[i * 64 + tt] * cvs[h * 64 + tt];
        } else v = 0.f;
        g_bcomb[i * NCB + t] = v;
    }
}

__global__ void setup_finblob_kernel()
{
    int i = blockIdx.x >> 1, part = blockIdx.x & 1;
    uint2* dst = g_Bfin + (size_t)i * 8704;
    int lo_i = part * 4352, hi_i = lo_i + 4352;
    const float* W = g_Wcomb + (size_t)i * 256 * NCB;
    for (int idx = lo_i + threadIdx.x; idx < hi_i; idx += 256) {
        int lane = idx & 31;
        int q  = idx >> 5;
        int nt = q % 17;
        int kt = q / 17;
        int n  = nt * 8 + (lane >> 2);
        int k0 = kt * 16 + (lane & 3) * 2;
        float w0 = W[(k0 + 0) * NCB + n], w1 = W[(k0 + 1) * NCB + n];
        float w8 = W[(k0 + 8) * NCB + n], w9 = W[(k0 + 9) * NCB + n];
        dst[idx] = make_uint2(pkh(w0, w1), pkh(w8, w9));
    }
}

// ============================ main kernel (4 warps, M=64, 2 CTAs/SM) ============================
// pair p = two chunks staged into the two 4352B slots of buffer (p&1). 128 threads.
// mid chunks are 4096B (512 uint2); fin chunks are 4352B (544 uint2).
// Consumer reads chunk `half` at byte offset half*4352.
__device__ __forceinline__ void stage_pair(char* smem, int p, int i, int t)
{
    char* dst = smem + SM_BBUF + (p & 1) * 8704;
    if (p < 32) {
        int layer = p >> 4, rem2 = p & 15;
        const char* src = (const char*)(g_Bmid + (size_t)(layer * Dn + i) * 16384 + (size_t)rem2 * 1024);
        #pragma unroll
        for (int u = 0; u < 2; u++) {
            int o = (t + u * 128) * 16;
            cpa16(dst + o,        src + o);
            cpa16(dst + 4352 + o, src + 4096 + o);
        }
    } else {
        const char* src = (const char*)(g_Bfin + (size_t)i * 8704 + (size_t)(p - 32) * 1088);
        #pragma unroll
        for (int u = 0; u < 5; u++) {
            int o = t + u * 128;
            if (o < 544) cpa16(dst + o * 16, src + o * 16);
        }
    }
}

__global__ void __launch_bounds__(128, 2) subnet_mma_kernel(
    const float* __restrict__ x, const float* __restrict__ W1,
    const float* __restrict__ b1, const float* __restrict__ bm)
{
    extern __shared__ char smem[];
    float* xs   = (float*)(smem + SM_X);
    float* w1s  = (float*)(smem + SM_W1);
    float* b1s  = (float*)(smem + SM_B1);
    float* bm0s = (float*)(smem + SM_BM0);
    float* bm1s = (float*)(smem + SM_BM1);
    float* bcs  = (float*)(smem + SM_BC);

    const int t = threadIdx.x, w = t >> 5, lane = t & 31;
    const int gr = lane >> 2, c = lane & 3;
    const int i  = blockIdx.y, r0 = blockIdx.x * 64;

    // stage pair 0 ASAP
    stage_pair(smem, 0, i, t);
    CPCOMMIT();

    // stage constants (128-thread strides)
    if (t < 64) xs[t] = x[(size_t)(r0 + t) * Dn + i];
    for (int idx = t; idx < 256; idx += 128) {
        w1s[idx]  = W1[i * 256 + idx];
        b1s[idx]  = b1[i * 256 + idx];
        bm0s[idx] = bm[(0 * Dn + i) * 256 + idx];
        bm1s[idx] = bm[(1 * Dn + i) * 256 + idx];
    }
    for (int idx = t; idx < NCB; idx += 128) bcs[idx] = g_bcomb[i * NCB + idx];
    __syncthreads();

    // ---- first layer: outer product -> A fragments (fp16, regs only) ----
    uint32_t Ahi[16][4];
    {
        float xa = xs[w * 16 + gr];
        float xb = xs[w * 16 + gr + 8];
        #pragma unroll
        for (int kt = 0; kt < 16; kt++) {
            int c0 = kt * 16 + 2 * c;
            float W0 = w1s[c0], W1v = w1s[c0 + 1], W8 = w1s[c0 + 8], W9 = w1s[c0 + 9];
            float B0 = b1s[c0], B1v = b1s[c0 + 1], B8 = b1s[c0 + 8], B9 = b1s[c0 + 9];
            Ahi[kt][0] = pkh(lrelu(fmaf(xa, W0, B0)), lrelu(fmaf(xa, W1v, B1v)));
            Ahi[kt][1] = pkh(lrelu(fmaf(xb, W0, B0)), lrelu(fmaf(xb, W1v, B1v)));
            Ahi[kt][2] = pkh(lrelu(fmaf(xa, W8, B8)), lrelu(fmaf(xa, W9, B9)));
            Ahi[kt][3] = pkh(lrelu(fmaf(xb, W8, B8)), lrelu(fmaf(xb, W9, B9)));
        }
    }

    // ---- two middle 256x256 layers ----
    #pragma unroll 1
    for (int layer = 0; layer < 2; layer++) {
        const float* bmls = (layer == 0) ? bm0s : bm1s;

        #pragma unroll
        for (int h = 0; h < 2; h++) {
            float acc[16][4];
            #pragma unroll
            for (int n_ = 0; n_ < 16; n_++)
                #pragma unroll
                for (int r = 0; r < 4; r++) acc[n_][r] = 0.f;

            #pragma unroll
            for (int ktp = 0; ktp < 8; ktp++) {
                const int p = layer * 16 + h * 8 + ktp;
                __syncthreads();   // consumers of pair p-1 done -> buffer (p+1)&1 free
                if (p < 39) { stage_pair(smem, p + 1, i, t); CPCOMMIT(); CPWAIT(1); }
                else        { CPWAIT(0); }
                __syncthreads();   // pair p fully staged for all threads

                const char* bb = smem + SM_BBUF + (p & 1) * 8704;
                #pragma unroll
                for (int half = 0; half < 2; half++) {
                    const char* bc2 = bb + half * 4352;
                    const int kt = 2 * ktp + half;
                    #pragma unroll
                    for (int ntl = 0; ntl < 16; ntl++) {
                        uint2 b2 = *(const uint2*)(bc2 + (ntl * 32 + lane) * 8);
                        mma16816(acc[ntl], Ahi[kt], b2.x, b2.y);
                    }
                }
            }

            // epilogue: bias + lrelu, pack -> smem A-frag slots (thread-private)
            #pragma unroll
            for (int j = 0; j < 8; j++) {
                int nt0 = 2 * j, nt1 = 2 * j + 1;
                int cb = 128 * h + 16 * j + 2 * c;
                float2 bb0 = *(const float2*)(bmls + cb);
                float2 bb1 = *(const float2*)(bmls + cb + 8);
                uint4 frag;
                frag.x = pkh(lrelu(acc[nt0][0] + bb0.x), lrelu(acc[nt0][1] + bb0.y));
                frag.y = pkh(lrelu(acc[nt0][2] + bb0.x), lrelu(acc[nt0][3] + bb0.y));
                frag.z = pkh(lrelu(acc[nt1][0] + bb1.x), lrelu(acc[nt1][1] + bb1.y));
                frag.w = pkh(lrelu(acc[nt1][2] + bb1.x), lrelu(acc[nt1][3] + bb1.y));
                *(uint4*)(smem + SM_ANX + (((w * 16) + 8 * h + j) * 32 + lane) * 16) = frag;
            }
        }

        // reload next-layer A-frags from thread-private smem slots (no sync needed)
        #pragma unroll
        for (int q = 0; q < 16; q++) {
            uint4 v = *(const uint4*)(smem + SM_ANX + ((w * 16 + q) * 32 + lane) * 16);
            Ahi[q][0] = v.x; Ahi[q][1] = v.y; Ahi[q][2] = v.z; Ahi[q][3] = v.w;
        }
    }

    // ---- final layer: 256 -> 136 (q | k | vs) ----
    {
        float fac[17][4];
        #pragma unroll
        for (int n_ = 0; n_ < 17; n_++)
            #pragma unroll
            for (int r = 0; r < 4; r++) fac[n_][r] = 0.f;

        #pragma unroll
        for (int ktp2 = 0; ktp2 < 8; ktp2++) {
            const int p = 32 + ktp2;
            __syncthreads();
            if (p < 39) { stage_pair(smem, p + 1, i, t); CPCOMMIT(); CPWAIT(1); }
            else        { CPWAIT(0); }
            __syncthreads();

            const char* bb = smem + SM_BBUF + (p & 1) * 8704;
            #pragma unroll
            for (int half = 0; half < 2; half++) {
                const char* bc2 = bb + half * 4352;
                const int kt = 2 * ktp2 + half;
                #pragma unroll
                for (int nt = 0; nt < 17; nt++) {
                    uint2 b2 = *(const uint2*)(bc2 + (nt * 32 + lane) * 8);
                    mma16816(fac[nt], Ahi[kt], b2.x, b2.y);
                }
            }
        }

        // epilogue: bias + scatter; q/k stored as fp16
        const int row0 = r0 + w * 16 + gr, row1 = row0 + 8;
        #pragma unroll
        for (int nt = 0; nt < 17; nt++) {
            int col = nt * 8 + 2 * c;
            float2 bb = *(const float2*)(bcs + col);
            float o0x = fac[nt][0] + bb.x, o0y = fac[nt][1] + bb.y;
            float o1x = fac[nt][2] + bb.x, o1y = fac[nt][3] + bb.y;
            if (nt < 8) {
                *(uint32_t*)&g_q[((size_t)row0 * Dn + i) * En + col] = pkh(o0x, o0y);
                *(uint32_t*)&g_q[((size_t)row1 * Dn + i) * En + col] = pkh(o1x, o1y);
            } else if (nt < 16) {
                *(uint32_t*)&g_k[((size_t)row0 * Dn + i) * En + (col - 64)] = pkh(o0x, o0y);
                *(uint32_t*)&g_k[((size_t)row1 * Dn + i) * En + (col - 64)] = pkh(o1x, o1y);
            } else if (c < 2) {
                *(float2*)&g_vs[((size_t)row0 * Dn + i) * 4 + (col - 128)] = make_float2(o0x, o0y);
                *(float2*)&g_vs[((size_t)row1 * Dn + i) * 4 + (col - 128)] = make_float2(o1x, o1y);
            }
        }
    }
}

// ============================ attention-lite kernel ============================
#define QS2 68
__global__ void __launch_bounds__(256, 2) attn_kernel(float* __restrict__ out)
{
    extern __shared__ float smemf[];
    const int t = threadIdx.x, wid = t >> 5, lane = t & 31;
    float* qs  = smemf + wid * (2 * Dn * QS2 + 68);
    float* ks  = qs + Dn * QS2;
    float* vss = ks + Dn * QS2;

    const int row = blockIdx.x * 8 + wid;
    const uint32_t* qr = (const uint32_t*)(g_q + (size_t)row * (Dn * En));
    const uint32_t* kr = (const uint32_t*)(g_k + (size_t)row * (Dn * En));

    #pragma unroll
    for (int u = 0; u < 17; u++) {
        int o = u * 32 + lane;             // half2 index 0..543
        int e2 = (o * 2) & 63;
        int ii = (o * 2) >> 6;
        float2 qf = __half22float2(*(const __half2*)&qr[o]);
        float2 kf = __half22float2(*(const __half2*)&kr[o]);
        qs[ii * QS2 + e2]     = qf.x;
        qs[ii * QS2 + e2 + 1] = qf.y;
        ks[ii * QS2 + e2]     = kf.x;
        ks[ii * QS2 + e2 + 1] = kf.y;
    }
    #pragma unroll
    for (int u = 0; u < 3; u++) {
        int p = u * 32 + lane;
        if (p < 68) vss[p] = g_vs[(size_t)row * 68 + p];
    }
    __syncwarp();

    float partial = 0.f;
    #pragma unroll
    for (int u = 0; u < 3; u++) {
        int p = u * 32 + lane;
        if (p < 68) {
            int h = p / 17, i1 = p - h * 17;
            const float* qv = qs + i1 * QS2 + h * 16;
            float s[17], smax = -1e30f;
            #pragma unroll
            for (int i2 = 0; i2 < 17; i2++) {
                const float* kv = ks + i2 * QS2 + h * 16;
                float d = 0.f;
                #pragma unroll
                for (int j = 0; j < 16; j++) d += qv[j] * kv[j];
                d *= 0.25f;
                s[i2] = d;
                smax = fmaxf(smax, d);
            }
            float den = 0.f, num = 0.f;
            #pragma unroll
            for (int i2 = 0; i2 < 17; i2++) {
                float e = __expf(s[i2] - smax);
                den += e;
                num += e * vss[i2 * 4 + h];
            }
            partial += num / den;
        }
    }
    #pragma unroll
    for (int off = 16; off; off >>= 1)
        partial += __shfl_down_sync(0xffffffffu, partial, off);
    if (lane == 0) out[row] = lrelu(partial * (1.f / 17.f) + g_const);
}

// ---------------------------------------------------------------------------
extern "C" void kernel_launch(void* const* d_in, const int* in_sizes, int n_in,
                              void* d_out, int out_size)
{
    const float* x   = (const float*)d_in[0];
    const float* W1  = (const float*)d_in[1];
    const float* b1  = (const float*)d_in[2];
    const float* Wm  = (const float*)d_in[3];
    const float* bm  = (const float*)d_in[4];
    const float* Wf  = (const float*)d_in[5];
    const float* bf  = (const float*)d_in[6];
    const float* Wq  = (const float*)d_in[7];
    const float* bq  = (const float*)d_in[8];
    const float* Wk  = (const float*)d_in[9];
    const float* bk  = (const float*)d_in[10];
    const float* Wv  = (const float*)d_in[11];
    const float* bv  = (const float*)d_in[12];
    const float* Wo  = (const float*)d_in[13];
    const float* bo  = (const float*)d_in[14];
    const float* Wfc = (const float*)d_in[15];
    const float* bfc = (const float*)d_in[16];
    float* out = (float*)d_out;

    const int k2_smem = 8 * (2 * Dn * QS2 + 68) * (int)sizeof(float);

    cudaFuncSetAttribute(subnet_mma_kernel, cudaFuncAttributeMaxDynamicSharedMemorySize, SM_TOTAL);
    cudaFuncSetAttribute(attn_kernel,       cudaFuncAttributeMaxDynamicSharedMemorySize, k2_smem);

    setup1_kernel<<<1, 64>>>(Wv, bv, Wo, bo, Wfc, bfc);
    setup2_mid_kernel<<<Dn + 2 * Dn * 8, 256>>>(Wf, bf, Wq, bq, Wk, bk, Wm);
    setup_finblob_kernel<<<Dn * 2, 256>>>();

    dim3 g1(Bn / 64, Dn);
    subnet_mma_kernel<<<g1, 128, SM_TOTAL>>>(x, W1, b1, bm);

    attn_kernel<<<Bn / 8, 256, k2_smem>>>(out);
}